// round 8
// baseline (speedup 1.0000x reference)
#include <cuda_runtime.h>
#include <math.h>
#include <cstdint>

#define BB 2
#define TT 1024
#define DD 1024
#define HH 16
#define HKV 8
#define HD 64
#define NL 3
#define MAXKV 3072
#define EPSI 1e-5f
#define NEGINF (-1e30f)

// ---------------- device scratch (static; no allocation) ----------------
__device__ float g_Q[BB*TT*DD];
__device__ float g_K[BB*MAXKV*HKV*HD];
__device__ float g_V[BB*MAXKV*HKV*HD];
__device__ float g_O[BB*TT*DD];
__device__ float g_acc[BB*TT*DD];
__device__ float g_y[BB*TT*DD];
__device__ float g_lw[NL];

// ================= tf32 mma.sync helpers ==============================
__device__ __forceinline__ uint32_t f2tf32(float x) {
    uint32_t u;
    asm("cvt.rna.tf32.f32 %0, %1;" : "=r"(u) : "f"(x));
    return u;
}

__device__ __forceinline__ void mma_16n8k8(float c[4], const uint32_t a[4], const uint32_t b[2]) {
    asm volatile("mma.sync.aligned.m16n8k8.row.col.f32.tf32.tf32.f32 "
        "{%0,%1,%2,%3}, {%4,%5,%6,%7}, {%8,%9}, {%0,%1,%2,%3};"
        : "+f"(c[0]), "+f"(c[1]), "+f"(c[2]), "+f"(c[3])
        : "r"(a[0]), "r"(a[1]), "r"(a[2]), "r"(a[3]), "r"(b[0]), "r"(b[1]));
}

// Paired-column layout: within each k-group of 8, column k is stored at
// position 2*(k&3) + ((k>>2)&1). Row stride 40 words -> LDS.64 frag loads
// are conflict-free per 16-lane phase. One buffer = 128*40 words.
#define RSTRIDE 40
#define GS (128*RSTRIDE)
#define GEMM_SMEM_BYTES (4*GS*4)   // 2 buffers x (A,W) x GS words x 4B = 81920

// stage K-chunk kt (32 cols) of A and W into smem buffers (tf32, paired layout)
__device__ __forceinline__ void stage_tiles(const float* __restrict__ A,
                                            const float* __restrict__ W,
                                            uint32_t* __restrict__ As,
                                            uint32_t* __restrict__ Ws,
                                            int kt, int tid) {
    #pragma unroll
    for (int j = 0; j < 4; j++) {
        int f = tid + j*256;
        int r = f >> 3;             // 0..127
        int cc = (f & 7)*4;         // 0,4,...,28
        float4 av = *(const float4*)(A + (size_t)r*DD + kt*32 + cc);
        float4 wv = *(const float4*)(W + (size_t)r*DD + kt*32 + cc);
        int base = r*RSTRIDE + (cc >> 3)*8 + ((cc & 4) ? 1 : 0);
        As[base+0] = f2tf32(av.x); As[base+2] = f2tf32(av.y);
        As[base+4] = f2tf32(av.z); As[base+6] = f2tf32(av.w);
        Ws[base+0] = f2tf32(wv.x); Ws[base+2] = f2tf32(wv.y);
        Ws[base+4] = f2tf32(wv.z); Ws[base+6] = f2tf32(wv.w);
    }
}

// mma over one staged K-chunk (32 cols = 4 x k8)
__device__ __forceinline__ void compute_chunk(const uint32_t* __restrict__ As,
                                              const uint32_t* __restrict__ Ws,
                                              float c[4][4][4],
                                              int lane, int wm0, int wn0) {
    int q = lane >> 2, cl = lane & 3;
    #pragma unroll
    for (int ks = 0; ks < 4; ks++) {
        uint32_t a[4][4], b[4][2];
        #pragma unroll
        for (int mi = 0; mi < 4; mi++) {
            int row = wm0 + mi*16 + q;
            uint2 lo = *(const uint2*)(As + row*RSTRIDE + ks*8 + 2*cl);
            uint2 hi = *(const uint2*)(As + (row+8)*RSTRIDE + ks*8 + 2*cl);
            a[mi][0] = lo.x; a[mi][1] = hi.x; a[mi][2] = lo.y; a[mi][3] = hi.y;
        }
        #pragma unroll
        for (int ni = 0; ni < 4; ni++) {
            int coln = wn0 + ni*8 + q;
            uint2 bb = *(const uint2*)(Ws + coln*RSTRIDE + ks*8 + 2*cl);
            b[ni][0] = bb.x; b[ni][1] = bb.y;
        }
        #pragma unroll
        for (int mi = 0; mi < 4; mi++)
            #pragma unroll
            for (int ni = 0; ni < 4; ni++)
                mma_16n8k8(c[mi][ni], a[mi], b[ni]);
    }
}

// C(128x128) = A(128x1024) * W(128x1024)^T; double-buffered; 1 sync/chunk.
__device__ __forceinline__ void tf32_mainloop(const float* __restrict__ A,
                                              const float* __restrict__ W,
                                              uint32_t* __restrict__ sh,
                                              float c[4][4][4],
                                              int tid, int lane, int wm0, int wn0) {
    uint32_t* As[2] = { sh,        sh + 2*GS };
    uint32_t* Ws[2] = { sh + GS,   sh + 3*GS };
    stage_tiles(A, W, As[0], Ws[0], 0, tid);
    __syncthreads();
    for (int kt = 0; kt < 32; kt++) {
        int cur = kt & 1;
        if (kt < 31) stage_tiles(A, W, As[cur^1], Ws[cur^1], kt+1, tid);
        compute_chunk(As[cur], Ws[cur], c, lane, wm0, wn0);
        __syncthreads();
    }
}

// ---------------- fused QKV projection (tf32 mma) ---------------------
__global__ __launch_bounds__(256, 2) void qkv_gemm_tc(const float* __restrict__ x,
                                                      const float* __restrict__ qw,
                                                      const float* __restrict__ kw,
                                                      const float* __restrict__ vw,
                                                      int layer) {
    extern __shared__ uint32_t sh[];
    int tid = threadIdx.x, lane = tid & 31, wid = tid >> 5;
    int wm0 = (wid >> 2)*64, wn0 = (wid & 3)*32;
    int bm = blockIdx.x, bn = blockIdx.y;
    const float* A = x + (size_t)bm*128*DD;
    const float* W;
    int mode, lc0;
    if (bn < 8)       { W = qw + (size_t)layer*DD*DD     + (size_t)bn*128*DD;      mode = 0; lc0 = bn*128; }
    else if (bn < 12) { W = kw + (size_t)layer*(DD/2)*DD + (size_t)(bn-8)*128*DD;  mode = 1; lc0 = (bn-8)*128; }
    else              { W = vw + (size_t)layer*(DD/2)*DD + (size_t)(bn-12)*128*DD; mode = 2; lc0 = (bn-12)*128; }

    float c[4][4][4];
    #pragma unroll
    for (int mi = 0; mi < 4; mi++)
        #pragma unroll
        for (int ni = 0; ni < 4; ni++)
            #pragma unroll
            for (int q = 0; q < 4; q++) c[mi][ni][q] = 0.f;

    tf32_mainloop(A, W, sh, c, tid, lane, wm0, wn0);

    float* kvbase = (mode == 1) ? g_K : g_V;
    #pragma unroll
    for (int mi = 0; mi < 4; mi++) {
        #pragma unroll
        for (int half = 0; half < 2; half++) {
            int mrow = bm*128 + wm0 + mi*16 + half*8 + (lane >> 2);
            float* dst;
            if (mode == 0) {
                dst = g_Q + (size_t)mrow*DD + lc0;
            } else {
                int b = mrow >> 10, t = mrow & 1023;
                dst = kvbase + ((size_t)(b*MAXKV + layer*TT + t))*(HKV*HD) + lc0;
            }
            #pragma unroll
            for (int ni = 0; ni < 4; ni++) {
                int col = wn0 + ni*8 + (lane & 3)*2;
                float2 v = half ? make_float2(c[mi][ni][2], c[mi][ni][3])
                                : make_float2(c[mi][ni][0], c[mi][ni][1]);
                *(float2*)(dst + col) = v;
            }
        }
    }
}

// ---------------- output projection (tf32 mma) ------------------------
__global__ __launch_bounds__(256, 2) void out_gemm_tc(const float* __restrict__ ow,
                                                      float* __restrict__ out) {
    extern __shared__ uint32_t sh[];
    int tid = threadIdx.x, lane = tid & 31, wid = tid >> 5;
    int wm0 = (wid >> 2)*64, wn0 = (wid & 3)*32;
    int bm = blockIdx.x, bn = blockIdx.y;
    const float* A = g_y + (size_t)bm*128*DD;
    const float* W = ow + (size_t)bn*128*DD;

    float c[4][4][4];
    #pragma unroll
    for (int mi = 0; mi < 4; mi++)
        #pragma unroll
        for (int ni = 0; ni < 4; ni++)
            #pragma unroll
            for (int q = 0; q < 4; q++) c[mi][ni][q] = 0.f;

    tf32_mainloop(A, W, sh, c, tid, lane, wm0, wn0);

    #pragma unroll
    for (int mi = 0; mi < 4; mi++) {
        #pragma unroll
        for (int half = 0; half < 2; half++) {
            int mrow = bm*128 + wm0 + mi*16 + half*8 + (lane >> 2);
            float* dst = out + (size_t)mrow*DD + bn*128;
            #pragma unroll
            for (int ni = 0; ni < 4; ni++) {
                int col = wn0 + ni*8 + (lane & 3)*2;
                float2 v = half ? make_float2(c[mi][ni][2], c[mi][ni][3])
                                : make_float2(c[mi][ni][0], c[mi][ni][1]);
                *(float2*)(dst + col) = v;
            }
        }
    }
}

// ---------------- lambda weights -------------------------------------
__global__ void compute_lw(const float* __restrict__ lam) {
    if (threadIdx.x == 0) {
        float s0 = 1.f/(1.f+expf(-lam[0]));
        float s1 = 1.f/(1.f+expf(-lam[1]));
        float s2 = 1.f/(1.f+expf(-lam[2]));
        float mean = (s0+s1+s2)*(1.f/3.f);
        float d0 = s0-mean, d1 = s1-mean, d2 = s2-mean;
        float var = (d0*d0+d1*d1+d2*d2)*(1.f/3.f);
        float r = rsqrtf(var + EPSI);
        g_lw[0] = d0*r; g_lw[1] = d1*r; g_lw[2] = d2*r;
    }
}

// ---------------- fused RoPE (Q + K) ----------------------------------
#define NQROPE (BB*TT*HH*32)
#define NKROPE (BB*TT*HKV*32)
__global__ void rope_qk(const float* __restrict__ cosT, const float* __restrict__ sinT, int layer) {
    int idx = blockIdx.x * blockDim.x + threadIdx.x;
    if (idx < NQROPE) {
        int d = idx & 31;
        int h = (idx >> 5) & 15;
        int t = (idx >> 9) & 1023;
        int b = idx >> 19;
        size_t base = ((size_t)(b*TT + t))*DD + h*HD + d;
        float x1 = g_Q[base], x2 = g_Q[base + 32];
        float c = cosT[t*32 + d], s = sinT[t*32 + d];
        g_Q[base]      = x1*c - x2*s;
        g_Q[base + 32] = x2*c + x1*s;
    } else {
        int k = idx - NQROPE;
        int d  = k & 31;
        int kh = (k >> 5) & 7;
        int t  = (k >> 8) & 1023;
        int b  = k >> 18;
        int p  = layer*TT + t;
        size_t base = ((size_t)(b*MAXKV + p))*(HKV*HD) + kh*HD + d;
        float x1 = g_K[base], x2 = g_K[base + 32];
        float c = cosT[p*32 + d], s = sinT[p*32 + d];
        g_K[base]      = x1*c - x2*s;
        g_K[base + 32] = x2*c + x1*s;
    }
}

// ---------------- flash attention (SIMT) ------------------------------
__device__ __forceinline__ void fma4s(float4& c, float s, float4 v) {
    c.x += s*v.x; c.y += s*v.y; c.z += s*v.z; c.w += s*v.w;
}

__global__ __launch_bounds__(256) void attn_kernel(int layer) {
    __shared__ float4 Qs[1024];
    __shared__ float4 Ks[1024];
    __shared__ float4 Vs[1024];
    int tid = threadIdx.x, tx = tid & 15, ty = tid >> 4;
    int qt = blockIdx.x, h = blockIdx.y, b = blockIdx.z;
    int t0 = qt * 64, kh = h >> 1;
    const float scale = 0.125f;

    #pragma unroll
    for (int j = 0; j < 4; j++) {
        int f = tid + j*256;
        int qr = f >> 4, d4 = f & 15;
        float4 v = *(const float4*)(g_Q + ((size_t)(b*TT + t0 + qr))*DD + h*HD + d4*4);
        v.x *= scale; v.y *= scale; v.z *= scale; v.w *= scale;
        Qs[qr*16 + (d4 ^ ((qr >> 2) & 7))] = v;
    }

    float4 oacc[4];
    float mrow[4], lrow[4];
    #pragma unroll
    for (int qi = 0; qi < 4; qi++) {
        oacc[qi] = make_float4(0.f,0.f,0.f,0.f);
        mrow[qi] = NEGINF; lrow[qi] = 0.f;
    }

    int ntiles = qt + layer*16 + 1;
    int swq = ty & 7, swk = tx & 7;

    for (int jt = 0; jt < ntiles; jt++) {
        __syncthreads();
        #pragma unroll
        for (int j = 0; j < 4; j++) {
            int f = tid + j*256;
            int kr = f >> 4, d4 = f & 15;
            size_t gro = ((size_t)(b*MAXKV + jt*64 + kr))*(HKV*HD) + kh*HD + d4*4;
            int sidx = kr*16 + (d4 ^ ((kr >> 2) & 7));
            Ks[sidx] = *(const float4*)(g_K + gro);
            Vs[sidx] = *(const float4*)(g_V + gro);
        }
        __syncthreads();

        float s[4][4];
        #pragma unroll
        for (int qi = 0; qi < 4; qi++)
            #pragma unroll
            for (int kj = 0; kj < 4; kj++) s[qi][kj] = 0.f;

        #pragma unroll
        for (int d4 = 0; d4 < 16; d4++) {
            float4 a0 = Qs[(ty*4+0)*16 + (d4 ^ swq)];
            float4 a1 = Qs[(ty*4+1)*16 + (d4 ^ swq)];
            float4 a2 = Qs[(ty*4+2)*16 + (d4 ^ swq)];
            float4 a3 = Qs[(ty*4+3)*16 + (d4 ^ swq)];
            float4 k0 = Ks[(tx*4+0)*16 + (d4 ^ swk)];
            float4 k1 = Ks[(tx*4+1)*16 + (d4 ^ swk)];
            float4 k2 = Ks[(tx*4+2)*16 + (d4 ^ swk)];
            float4 k3 = Ks[(tx*4+3)*16 + (d4 ^ swk)];
            s[0][0] += a0.x*k0.x + a0.y*k0.y + a0.z*k0.z + a0.w*k0.w;
            s[0][1] += a0.x*k1.x + a0.y*k1.y + a0.z*k1.z + a0.w*k1.w;
            s[0][2] += a0.x*k2.x + a0.y*k2.y + a0.z*k2.z + a0.w*k2.w;
            s[0][3] += a0.x*k3.x + a0.y*k3.y + a0.z*k3.z + a0.w*k3.w;
            s[1][0] += a1.x*k0.x + a1.y*k0.y + a1.z*k0.z + a1.w*k0.w;
            s[1][1] += a1.x*k1.x + a1.y*k1.y + a1.z*k1.z + a1.w*k1.w;
            s[1][2] += a1.x*k2.x + a1.y*k2.y + a1.z*k2.z + a1.w*k2.w;
            s[1][3] += a1.x*k3.x + a1.y*k3.y + a1.z*k3.z + a1.w*k3.w;
            s[2][0] += a2.x*k0.x + a2.y*k0.y + a2.z*k0.z + a2.w*k0.w;
            s[2][1] += a2.x*k1.x + a2.y*k1.y + a2.z*k1.z + a2.w*k1.w;
            s[2][2] += a2.x*k2.x + a2.y*k2.y + a2.z*k2.z + a2.w*k2.w;
            s[2][3] += a2.x*k3.x + a2.y*k3.y + a2.z*k3.z + a2.w*k3.w;
            s[3][0] += a3.x*k0.x + a3.y*k0.y + a3.z*k0.z + a3.w*k0.w;
            s[3][1] += a3.x*k1.x + a3.y*k1.y + a3.z*k1.z + a3.w*k1.w;
            s[3][2] += a3.x*k2.x + a3.y*k2.y + a3.z*k2.z + a3.w*k2.w;
            s[3][3] += a3.x*k3.x + a3.y*k3.y + a3.z*k3.z + a3.w*k3.w;
        }

        #pragma unroll
        for (int qi = 0; qi < 4; qi++) {
            int lim = t0 + ty*4 + qi + layer*TT;
            int kg = jt*64 + tx*4;
            if (kg + 0 > lim) s[qi][0] = NEGINF;
            if (kg + 1 > lim) s[qi][1] = NEGINF;
            if (kg + 2 > lim) s[qi][2] = NEGINF;
            if (kg + 3 > lim) s[qi][3] = NEGINF;
            float mx = fmaxf(fmaxf(s[qi][0], s[qi][1]), fmaxf(s[qi][2], s[qi][3]));
            mx = fmaxf(mx, __shfl_xor_sync(0xffffffffu, mx, 1));
            mx = fmaxf(mx, __shfl_xor_sync(0xffffffffu, mx, 2));
            mx = fmaxf(mx, __shfl_xor_sync(0xffffffffu, mx, 4));
            mx = fmaxf(mx, __shfl_xor_sync(0xffffffffu, mx, 8));
            float mnew = fmaxf(mrow[qi], mx);
            float corr = __expf(mrow[qi] - mnew);
            mrow[qi] = mnew;
            float rs = 0.f;
            #pragma unroll
            for (int kj = 0; kj < 4; kj++) {
                s[qi][kj] = __expf(s[qi][kj] - mnew);
                rs += s[qi][kj];
            }
            rs += __shfl_xor_sync(0xffffffffu, rs, 1);
            rs += __shfl_xor_sync(0xffffffffu, rs, 2);
            rs += __shfl_xor_sync(0xffffffffu, rs, 4);
            rs += __shfl_xor_sync(0xffffffffu, rs, 8);
            lrow[qi] = lrow[qi]*corr + rs;
            oacc[qi].x *= corr; oacc[qi].y *= corr; oacc[qi].z *= corr; oacc[qi].w *= corr;
        }

        __syncthreads();
        #pragma unroll
        for (int qi = 0; qi < 4; qi++)
            Ks[(ty*4+qi)*16 + (tx ^ swq)] = make_float4(s[qi][0], s[qi][1], s[qi][2], s[qi][3]);
        __syncthreads();

        #pragma unroll
        for (int k4 = 0; k4 < 16; k4++) {
            float4 p0 = Ks[(ty*4+0)*16 + (k4 ^ swq)];
            float4 p1 = Ks[(ty*4+1)*16 + (k4 ^ swq)];
            float4 p2 = Ks[(ty*4+2)*16 + (k4 ^ swq)];
            float4 p3 = Ks[(ty*4+3)*16 + (k4 ^ swq)];
            int swv = k4 & 7;
            float4 v0 = Vs[(k4*4+0)*16 + (tx ^ swv)];
            float4 v1 = Vs[(k4*4+1)*16 + (tx ^ swv)];
            float4 v2 = Vs[(k4*4+2)*16 + (tx ^ swv)];
            float4 v3 = Vs[(k4*4+3)*16 + (tx ^ swv)];
            fma4s(oacc[0], p0.x, v0); fma4s(oacc[0], p0.y, v1); fma4s(oacc[0], p0.z, v2); fma4s(oacc[0], p0.w, v3);
            fma4s(oacc[1], p1.x, v0); fma4s(oacc[1], p1.y, v1); fma4s(oacc[1], p1.z, v2); fma4s(oacc[1], p1.w, v3);
            fma4s(oacc[2], p2.x, v0); fma4s(oacc[2], p2.y, v1); fma4s(oacc[2], p2.z, v2); fma4s(oacc[2], p2.w, v3);
            fma4s(oacc[3], p3.x, v0); fma4s(oacc[3], p3.y, v1); fma4s(oacc[3], p3.z, v2); fma4s(oacc[3], p3.w, v3);
        }
    }

    #pragma unroll
    for (int qi = 0; qi < 4; qi++) {
        float inv = 1.0f / lrow[qi];
        float4 v = oacc[qi];
        v.x *= inv; v.y *= inv; v.z *= inv; v.w *= inv;
        *(float4*)(g_O + ((size_t)(b*TT + t0 + ty*4 + qi))*DD + h*HD + tx*4) = v;
    }
}

// ---------------- row reductions -------------------------------------
__device__ __forceinline__ float block_reduce_sum(float v, float* red, int tid) {
    v += __shfl_xor_sync(0xffffffffu, v, 16);
    v += __shfl_xor_sync(0xffffffffu, v, 8);
    v += __shfl_xor_sync(0xffffffffu, v, 4);
    v += __shfl_xor_sync(0xffffffffu, v, 2);
    v += __shfl_xor_sync(0xffffffffu, v, 1);
    if ((tid & 31) == 0) red[tid >> 5] = v;
    __syncthreads();
    if (tid < 32) {
        float w = (tid < 8) ? red[tid] : 0.f;
        w += __shfl_xor_sync(0xffffffffu, w, 4);
        w += __shfl_xor_sync(0xffffffffu, w, 2);
        w += __shfl_xor_sync(0xffffffffu, w, 1);
        if (tid == 0) red[0] = w;
    }
    __syncthreads();
    return red[0];
}

__global__ __launch_bounds__(256) void rmsnorm_acc(const float* __restrict__ lnw, int layer) {
    __shared__ float red[8];
    int row = blockIdx.x, tid = threadIdx.x;
    float4 o = *(const float4*)(g_O + (size_t)row*DD + tid*4);
    float ss = o.x*o.x + o.y*o.y + o.z*o.z + o.w*o.w;
    float total = block_reduce_sum(ss, red, tid);
    float r = rsqrtf(total * (1.0f/DD) + EPSI) * g_lw[layer];
    float4 w = *(const float4*)(lnw + (size_t)layer*DD + tid*4);
    float4 res = make_float4(o.x*r*w.x, o.y*r*w.y, o.z*r*w.z, o.w*r*w.w);
    float* ap = g_acc + (size_t)row*DD + tid*4;
    if (layer == 0) {
        *(float4*)ap = res;
    } else {
        float4 a = *(const float4*)ap;
        a.x += res.x; a.y += res.y; a.z += res.z; a.w += res.w;
        *(float4*)ap = a;
    }
}

__global__ __launch_bounds__(256) void final_norm(const float* __restrict__ x,
                                                  const float* __restrict__ flnw,
                                                  const float* __restrict__ alpha) {
    __shared__ float red[8];
    int row = blockIdx.x, tid = threadIdx.x;
    float al = alpha[0];
    float4 a = *(const float4*)(g_acc + (size_t)row*DD + tid*4);
    float4 xv = *(const float4*)(x + (size_t)row*DD + tid*4);
    float4 v = make_float4(a.x + al*xv.x, a.y + al*xv.y, a.z + al*xv.z, a.w + al*xv.w);
    float ss = v.x*v.x + v.y*v.y + v.z*v.z + v.w*v.w;
    float total = block_reduce_sum(ss, red, tid);
    float r = rsqrtf(total * (1.0f/DD) + EPSI);
    float4 w = *(const float4*)(flnw + tid*4);
    float4 res = make_float4(v.x*r*w.x, v.y*r*w.y, v.z*r*w.z, v.w*r*w.w);
    *(float4*)(g_y + (size_t)row*DD + tid*4) = res;
}

// ---------------- launch ---------------------------------------------
extern "C" void kernel_launch(void* const* d_in, const int* in_sizes, int n_in,
                              void* d_out, int out_size) {
    const float* x    = (const float*)d_in[0];
    const float* cosT = (const float*)d_in[1];
    const float* sinT = (const float*)d_in[2];
    const float* qw   = (const float*)d_in[3];
    const float* kw   = (const float*)d_in[4];
    const float* vw   = (const float*)d_in[5];
    const float* lnw  = (const float*)d_in[6];
    const float* lam  = (const float*)d_in[7];
    const float* ow   = (const float*)d_in[8];
    const float* flnw = (const float*)d_in[9];
    const float* alpha= (const float*)d_in[10];
    float* out = (float*)d_out;

    cudaFuncSetAttribute(qkv_gemm_tc, cudaFuncAttributeMaxDynamicSharedMemorySize, GEMM_SMEM_BYTES);
    cudaFuncSetAttribute(out_gemm_tc, cudaFuncAttributeMaxDynamicSharedMemorySize, GEMM_SMEM_BYTES);

    compute_lw<<<1, 32>>>(lam);

    for (int layer = 0; layer < NL; layer++) {
        qkv_gemm_tc<<<dim3(16, 16), 256, GEMM_SMEM_BYTES>>>(x, qw, kw, vw, layer);
        rope_qk<<<(NQROPE + NKROPE)/256, 256>>>(cosT, sinT, layer);
        attn_kernel<<<dim3(16, HH, BB), 256>>>(layer);
        rmsnorm_acc<<<BB*TT, 256>>>(lnw, layer);
    }

    final_norm<<<BB*TT, 256>>>(x, flnw, alpha);
    out_gemm_tc<<<dim3(16, 8), 256, GEMM_SMEM_BYTES>>>(ow, out);
}

// round 9
// speedup vs baseline: 2.1353x; 2.1353x over previous
#include <cuda_runtime.h>
#include <math.h>
#include <cstdint>

#define BB 2
#define TT 1024
#define DD 1024
#define HH 16
#define HKV 8
#define HD 64
#define NL 3
#define MAXKV 3072
#define EPSI 1e-5f
#define NEGINF (-1e30f)

// ---------------- device scratch (static; no allocation) ----------------
__device__ float g_Q[BB*TT*DD];
__device__ float g_K[BB*MAXKV*HKV*HD];
__device__ float g_V[BB*MAXKV*HKV*HD];
__device__ float g_O[BB*TT*DD];
__device__ float g_acc[BB*TT*DD];
__device__ float g_y[BB*TT*DD];
__device__ float g_lw[NL];

// ================= tf32 mma.sync helpers ==============================
__device__ __forceinline__ uint32_t f2tf32(float x) {
    uint32_t u;
    asm("cvt.rna.tf32.f32 %0, %1;" : "=r"(u) : "f"(x));
    return u;
}

__device__ __forceinline__ void mma_16n8k8(float c[4], const uint32_t a[4], const uint32_t b[2]) {
    asm volatile("mma.sync.aligned.m16n8k8.row.col.f32.tf32.tf32.f32 "
        "{%0,%1,%2,%3}, {%4,%5,%6,%7}, {%8,%9}, {%0,%1,%2,%3};"
        : "+f"(c[0]), "+f"(c[1]), "+f"(c[2]), "+f"(c[3])
        : "r"(a[0]), "r"(a[1]), "r"(a[2]), "r"(a[3]), "r"(b[0]), "r"(b[1]));
}

// ======================================================================
//                      GEMM (R6 proven version)
// ======================================================================
#define SSTRIDE 36

__device__ __forceinline__ void tf32_mainloop(const float* __restrict__ A,
                                              const float* __restrict__ W,
                                              uint32_t* As, uint32_t* Ws,
                                              float c[4][4][4],
                                              int tid, int lane, int wm0, int wn0) {
    for (int kt = 0; kt < 32; kt++) {
        #pragma unroll
        for (int j = 0; j < 4; j++) {
            int f = tid + j*256;
            int r = f >> 3, cc = (f & 7)*4;
            float4 av = *(const float4*)(A + (size_t)r*DD + kt*32 + cc);
            float4 wv = *(const float4*)(W + (size_t)r*DD + kt*32 + cc);
            uint32_t* pa = As + r*SSTRIDE + cc;
            pa[0] = f2tf32(av.x); pa[1] = f2tf32(av.y); pa[2] = f2tf32(av.z); pa[3] = f2tf32(av.w);
            uint32_t* pw = Ws + r*SSTRIDE + cc;
            pw[0] = f2tf32(wv.x); pw[1] = f2tf32(wv.y); pw[2] = f2tf32(wv.z); pw[3] = f2tf32(wv.w);
        }
        __syncthreads();
        #pragma unroll
        for (int ks = 0; ks < 4; ks++) {
            int k0 = ks*8;
            uint32_t a[4][4], b[4][2];
            #pragma unroll
            for (int mi = 0; mi < 4; mi++) {
                int row = wm0 + mi*16 + (lane >> 2);
                const uint32_t* p = As + row*SSTRIDE + k0 + (lane & 3);
                a[mi][0] = p[0];
                a[mi][1] = p[8*SSTRIDE];
                a[mi][2] = p[4];
                a[mi][3] = p[8*SSTRIDE + 4];
            }
            #pragma unroll
            for (int ni = 0; ni < 4; ni++) {
                int coln = wn0 + ni*8 + (lane >> 2);
                const uint32_t* p = Ws + coln*SSTRIDE + k0 + (lane & 3);
                b[ni][0] = p[0];
                b[ni][1] = p[4];
            }
            #pragma unroll
            for (int mi = 0; mi < 4; mi++)
                #pragma unroll
                for (int ni = 0; ni < 4; ni++)
                    mma_16n8k8(c[mi][ni], a[mi], b[ni]);
        }
        __syncthreads();
    }
}

__global__ __launch_bounds__(256) void qkv_gemm_tc(const float* __restrict__ x,
                                                   const float* __restrict__ qw,
                                                   const float* __restrict__ kw,
                                                   const float* __restrict__ vw,
                                                   int layer) {
    __shared__ uint32_t As[128*SSTRIDE];
    __shared__ uint32_t Ws[128*SSTRIDE];
    int tid = threadIdx.x, lane = tid & 31, wid = tid >> 5;
    int wm0 = (wid >> 2)*64, wn0 = (wid & 3)*32;
    int bm = blockIdx.x, bn = blockIdx.y;
    const float* A = x + (size_t)bm*128*DD;
    const float* W;
    int mode, lc0;
    if (bn < 8)       { W = qw + (size_t)layer*DD*DD     + (size_t)bn*128*DD;      mode = 0; lc0 = bn*128; }
    else if (bn < 12) { W = kw + (size_t)layer*(DD/2)*DD + (size_t)(bn-8)*128*DD;  mode = 1; lc0 = (bn-8)*128; }
    else              { W = vw + (size_t)layer*(DD/2)*DD + (size_t)(bn-12)*128*DD; mode = 2; lc0 = (bn-12)*128; }

    float c[4][4][4];
    #pragma unroll
    for (int mi = 0; mi < 4; mi++)
        #pragma unroll
        for (int ni = 0; ni < 4; ni++)
            #pragma unroll
            for (int q = 0; q < 4; q++) c[mi][ni][q] = 0.f;

    tf32_mainloop(A, W, As, Ws, c, tid, lane, wm0, wn0);

    float* kvbase = (mode == 1) ? g_K : g_V;
    #pragma unroll
    for (int mi = 0; mi < 4; mi++) {
        #pragma unroll
        for (int half = 0; half < 2; half++) {
            int mrow = bm*128 + wm0 + mi*16 + half*8 + (lane >> 2);
            float* dst;
            if (mode == 0) {
                dst = g_Q + (size_t)mrow*DD + lc0;
            } else {
                int b = mrow >> 10, t = mrow & 1023;
                dst = kvbase + ((size_t)(b*MAXKV + layer*TT + t))*(HKV*HD) + lc0;
            }
            #pragma unroll
            for (int ni = 0; ni < 4; ni++) {
                int col = wn0 + ni*8 + (lane & 3)*2;
                float2 v = half ? make_float2(c[mi][ni][2], c[mi][ni][3])
                                : make_float2(c[mi][ni][0], c[mi][ni][1]);
                *(float2*)(dst + col) = v;
            }
        }
    }
}

__global__ __launch_bounds__(256) void out_gemm_tc(const float* __restrict__ ow,
                                                   float* __restrict__ out) {
    __shared__ uint32_t As[128*SSTRIDE];
    __shared__ uint32_t Ws[128*SSTRIDE];
    int tid = threadIdx.x, lane = tid & 31, wid = tid >> 5;
    int wm0 = (wid >> 2)*64, wn0 = (wid & 3)*32;
    int bm = blockIdx.x, bn = blockIdx.y;
    const float* A = g_y + (size_t)bm*128*DD;
    const float* W = ow + (size_t)bn*128*DD;

    float c[4][4][4];
    #pragma unroll
    for (int mi = 0; mi < 4; mi++)
        #pragma unroll
        for (int ni = 0; ni < 4; ni++)
            #pragma unroll
            for (int q = 0; q < 4; q++) c[mi][ni][q] = 0.f;

    tf32_mainloop(A, W, As, Ws, c, tid, lane, wm0, wn0);

    #pragma unroll
    for (int mi = 0; mi < 4; mi++) {
        #pragma unroll
        for (int half = 0; half < 2; half++) {
            int mrow = bm*128 + wm0 + mi*16 + half*8 + (lane >> 2);
            float* dst = out + (size_t)mrow*DD + bn*128;
            #pragma unroll
            for (int ni = 0; ni < 4; ni++) {
                int col = wn0 + ni*8 + (lane & 3)*2;
                float2 v = half ? make_float2(c[mi][ni][2], c[mi][ni][3])
                                : make_float2(c[mi][ni][0], c[mi][ni][1]);
                *(float2*)(dst + col) = v;
            }
        }
    }
}

// ======================================================================
//                  Flash attention on mma.sync tf32
// ======================================================================
// Q-tile 128 rows, KV-tile 64. 8 warps; warp w owns Q-rows [16w,16w+16).
// Smem: Qs(128x64), Ks(64x64), VsT(64x64 transposed), Ps(128x64), all
// tf32 u32 with row stride 68 (frag loads bank-conflict-free).
#define ASTR 68
#define AQ_OFF 0
#define AK_OFF (128*ASTR)
#define AV_OFF (AK_OFF + 64*ASTR)
#define AP_OFF (AV_OFF + 64*ASTR)
#define ATTN_SMEM ((AP_OFF + 128*ASTR)*4)

__global__ __launch_bounds__(256) void attn_mma(int layer) {
    extern __shared__ uint32_t sm[];
    uint32_t* Qs  = sm + AQ_OFF;
    uint32_t* Ks  = sm + AK_OFF;
    uint32_t* VsT = sm + AV_OFF;
    uint32_t* Ps  = sm + AP_OFF;
    int tid = threadIdx.x, lane = tid & 31, wid = tid >> 5;
    int qt = blockIdx.x, h = blockIdx.y, b = blockIdx.z;
    int kh = h >> 1;
    int t0 = qt*128, m0 = wid*16;
    int q = lane >> 2, cl = lane & 3;
    const float qscale = 0.125f * 1.44269504f;   // HD^-0.5 * log2(e): exp2 domain

    // ---- stage Q (scaled, tf32) ----
    #pragma unroll
    for (int j = 0; j < 8; j++) {
        int f = tid + j*256;
        int r = f >> 4, c4 = (f & 15)*4;
        float4 v = *(const float4*)(g_Q + ((size_t)(b*TT + t0 + r))*DD + h*HD + c4);
        uint4 u;
        u.x = f2tf32(v.x*qscale); u.y = f2tf32(v.y*qscale);
        u.z = f2tf32(v.z*qscale); u.w = f2tf32(v.w*qscale);
        *(uint4*)(Qs + r*ASTR + c4) = u;
    }

    float occ[8][4];
    #pragma unroll
    for (int nt = 0; nt < 8; nt++)
        #pragma unroll
        for (int e = 0; e < 4; e++) occ[nt][e] = 0.f;
    float m0r = NEGINF, m1r = NEGINF, l0r = 0.f, l1r = 0.f;

    int ntiles = 2*qt + 2 + layer*16;
    int lim0 = t0 + m0 + q + layer*TT;
    int lim1 = lim0 + 8;

    // V staging map: thread -> (kv = tid&63, hd block = (tid>>6)*16)
    int vkv = tid & 63, vhd0 = (tid >> 6)*16;

    for (int jt = 0; jt < ntiles; jt++) {
        __syncthreads();
        // stage K (row-major kv x hd)
        #pragma unroll
        for (int j = 0; j < 4; j++) {
            int f = tid + j*256;
            int r = f >> 4, c4 = (f & 15)*4;
            float4 v = *(const float4*)(g_K + ((size_t)(b*MAXKV + jt*64 + r))*(HKV*HD) + kh*HD + c4);
            uint4 u; u.x = f2tf32(v.x); u.y = f2tf32(v.y); u.z = f2tf32(v.z); u.w = f2tf32(v.w);
            *(uint4*)(Ks + r*ASTR + c4) = u;
        }
        // stage V transposed: VsT[hd][kv]
        {
            const float* vp = g_V + ((size_t)(b*MAXKV + jt*64 + vkv))*(HKV*HD) + kh*HD + vhd0;
            #pragma unroll
            for (int jj = 0; jj < 4; jj++) {
                float4 v = *(const float4*)(vp + jj*4);
                VsT[(vhd0 + jj*4 + 0)*ASTR + vkv] = f2tf32(v.x);
                VsT[(vhd0 + jj*4 + 1)*ASTR + vkv] = f2tf32(v.y);
                VsT[(vhd0 + jj*4 + 2)*ASTR + vkv] = f2tf32(v.z);
                VsT[(vhd0 + jj*4 + 3)*ASTR + vkv] = f2tf32(v.w);
            }
        }
        __syncthreads();

        // ---- S = Q · K^T  (warp: 16 x 64) ----
        float s[8][4];
        #pragma unroll
        for (int nt = 0; nt < 8; nt++) { s[nt][0]=0.f; s[nt][1]=0.f; s[nt][2]=0.f; s[nt][3]=0.f; }
        #pragma unroll
        for (int ks = 0; ks < 8; ks++) {
            uint32_t a[4];
            const uint32_t* ap = Qs + (m0 + q)*ASTR + ks*8 + cl;
            a[0] = ap[0]; a[1] = ap[8*ASTR]; a[2] = ap[4]; a[3] = ap[8*ASTR + 4];
            #pragma unroll
            for (int nt = 0; nt < 8; nt++) {
                const uint32_t* bp = Ks + (nt*8 + q)*ASTR + ks*8 + cl;
                uint32_t bb[2] = { bp[0], bp[4] };
                mma_16n8k8(s[nt], a, bb);
            }
        }

        // ---- mask + online softmax (exp2 domain) ----
        int kbase = jt*64;
        float mx0 = NEGINF, mx1 = NEGINF;
        #pragma unroll
        for (int nt = 0; nt < 8; nt++) {
            int k0 = kbase + nt*8 + 2*cl;
            if (k0     > lim0) s[nt][0] = NEGINF;
            if (k0 + 1 > lim0) s[nt][1] = NEGINF;
            if (k0     > lim1) s[nt][2] = NEGINF;
            if (k0 + 1 > lim1) s[nt][3] = NEGINF;
            mx0 = fmaxf(mx0, fmaxf(s[nt][0], s[nt][1]));
            mx1 = fmaxf(mx1, fmaxf(s[nt][2], s[nt][3]));
        }
        mx0 = fmaxf(mx0, __shfl_xor_sync(0xffffffffu, mx0, 1));
        mx0 = fmaxf(mx0, __shfl_xor_sync(0xffffffffu, mx0, 2));
        mx1 = fmaxf(mx1, __shfl_xor_sync(0xffffffffu, mx1, 1));
        mx1 = fmaxf(mx1, __shfl_xor_sync(0xffffffffu, mx1, 2));
        float mn0 = fmaxf(m0r, mx0), mn1 = fmaxf(m1r, mx1);
        float cor0 = exp2f(m0r - mn0), cor1 = exp2f(m1r - mn1);
        m0r = mn0; m1r = mn1;
        float rs0 = 0.f, rs1 = 0.f;
        #pragma unroll
        for (int nt = 0; nt < 8; nt++) {
            s[nt][0] = exp2f(s[nt][0] - mn0); s[nt][1] = exp2f(s[nt][1] - mn0);
            s[nt][2] = exp2f(s[nt][2] - mn1); s[nt][3] = exp2f(s[nt][3] - mn1);
            rs0 += s[nt][0] + s[nt][1];
            rs1 += s[nt][2] + s[nt][3];
            uint32_t* pp = Ps + (m0 + q)*ASTR + nt*8 + 2*cl;
            *(uint2*)pp            = make_uint2(f2tf32(s[nt][0]), f2tf32(s[nt][1]));
            *(uint2*)(pp + 8*ASTR) = make_uint2(f2tf32(s[nt][2]), f2tf32(s[nt][3]));
            occ[nt][0] *= cor0; occ[nt][1] *= cor0;
            occ[nt][2] *= cor1; occ[nt][3] *= cor1;
        }
        rs0 += __shfl_xor_sync(0xffffffffu, rs0, 1);
        rs0 += __shfl_xor_sync(0xffffffffu, rs0, 2);
        rs1 += __shfl_xor_sync(0xffffffffu, rs1, 1);
        rs1 += __shfl_xor_sync(0xffffffffu, rs1, 2);
        l0r = l0r*cor0 + rs0;
        l1r = l1r*cor1 + rs1;

        // ---- O += P · V  (warp-private P rows; no sync needed) ----
        #pragma unroll
        for (int ks = 0; ks < 8; ks++) {
            uint32_t a[4];
            const uint32_t* ap = Ps + (m0 + q)*ASTR + ks*8 + cl;
            a[0] = ap[0]; a[1] = ap[8*ASTR]; a[2] = ap[4]; a[3] = ap[8*ASTR + 4];
            #pragma unroll
            for (int nt = 0; nt < 8; nt++) {
                const uint32_t* bp = VsT + (nt*8 + q)*ASTR + ks*8 + cl;
                uint32_t bb[2] = { bp[0], bp[4] };
                mma_16n8k8(occ[nt], a, bb);
            }
        }
    }

    // ---- epilogue ----
    float inv0 = 1.0f / l0r, inv1 = 1.0f / l1r;
    #pragma unroll
    for (int nt = 0; nt < 8; nt++) {
        float* d0 = g_O + ((size_t)(b*TT + t0 + m0 + q))*DD + h*HD + nt*8 + 2*cl;
        *(float2*)d0 = make_float2(occ[nt][0]*inv0, occ[nt][1]*inv0);
        *(float2*)(d0 + 8*DD) = make_float2(occ[nt][2]*inv1, occ[nt][3]*inv1);
    }
}

// ---------------- lambda weights -------------------------------------
__global__ void compute_lw(const float* __restrict__ lam) {
    if (threadIdx.x == 0) {
        float s0 = 1.f/(1.f+expf(-lam[0]));
        float s1 = 1.f/(1.f+expf(-lam[1]));
        float s2 = 1.f/(1.f+expf(-lam[2]));
        float mean = (s0+s1+s2)*(1.f/3.f);
        float d0 = s0-mean, d1 = s1-mean, d2 = s2-mean;
        float var = (d0*d0+d1*d1+d2*d2)*(1.f/3.f);
        float r = rsqrtf(var + EPSI);
        g_lw[0] = d0*r; g_lw[1] = d1*r; g_lw[2] = d2*r;
    }
}

// ---------------- fused RoPE (Q + K) ----------------------------------
#define NQROPE (BB*TT*HH*32)
#define NKROPE (BB*TT*HKV*32)
__global__ void rope_qk(const float* __restrict__ cosT, const float* __restrict__ sinT, int layer) {
    int idx = blockIdx.x * blockDim.x + threadIdx.x;
    if (idx < NQROPE) {
        int d = idx & 31;
        int h = (idx >> 5) & 15;
        int t = (idx >> 9) & 1023;
        int b = idx >> 19;
        size_t base = ((size_t)(b*TT + t))*DD + h*HD + d;
        float x1 = g_Q[base], x2 = g_Q[base + 32];
        float c = cosT[t*32 + d], s = sinT[t*32 + d];
        g_Q[base]      = x1*c - x2*s;
        g_Q[base + 32] = x2*c + x1*s;
    } else {
        int k = idx - NQROPE;
        int d  = k & 31;
        int kh = (k >> 5) & 7;
        int t  = (k >> 8) & 1023;
        int b  = k >> 18;
        int p  = layer*TT + t;
        size_t base = ((size_t)(b*MAXKV + p))*(HKV*HD) + kh*HD + d;
        float x1 = g_K[base], x2 = g_K[base + 32];
        float c = cosT[p*32 + d], s = sinT[p*32 + d];
        g_K[base]      = x1*c - x2*s;
        g_K[base + 32] = x2*c + x1*s;
    }
}

// ---------------- row reductions -------------------------------------
__device__ __forceinline__ float block_reduce_sum(float v, float* red, int tid) {
    v += __shfl_xor_sync(0xffffffffu, v, 16);
    v += __shfl_xor_sync(0xffffffffu, v, 8);
    v += __shfl_xor_sync(0xffffffffu, v, 4);
    v += __shfl_xor_sync(0xffffffffu, v, 2);
    v += __shfl_xor_sync(0xffffffffu, v, 1);
    if ((tid & 31) == 0) red[tid >> 5] = v;
    __syncthreads();
    if (tid < 32) {
        float w = (tid < 8) ? red[tid] : 0.f;
        w += __shfl_xor_sync(0xffffffffu, w, 4);
        w += __shfl_xor_sync(0xffffffffu, w, 2);
        w += __shfl_xor_sync(0xffffffffu, w, 1);
        if (tid == 0) red[0] = w;
    }
    __syncthreads();
    return red[0];
}

__global__ __launch_bounds__(256) void rmsnorm_acc(const float* __restrict__ lnw, int layer) {
    __shared__ float red[8];
    int row = blockIdx.x, tid = threadIdx.x;
    float4 o = *(const float4*)(g_O + (size_t)row*DD + tid*4);
    float ss = o.x*o.x + o.y*o.y + o.z*o.z + o.w*o.w;
    float total = block_reduce_sum(ss, red, tid);
    float r = rsqrtf(total * (1.0f/DD) + EPSI) * g_lw[layer];
    float4 w = *(const float4*)(lnw + (size_t)layer*DD + tid*4);
    float4 res = make_float4(o.x*r*w.x, o.y*r*w.y, o.z*r*w.z, o.w*r*w.w);
    float* ap = g_acc + (size_t)row*DD + tid*4;
    if (layer == 0) {
        *(float4*)ap = res;
    } else {
        float4 a = *(const float4*)ap;
        a.x += res.x; a.y += res.y; a.z += res.z; a.w += res.w;
        *(float4*)ap = a;
    }
}

__global__ __launch_bounds__(256) void final_norm(const float* __restrict__ x,
                                                  const float* __restrict__ flnw,
                                                  const float* __restrict__ alpha) {
    __shared__ float red[8];
    int row = blockIdx.x, tid = threadIdx.x;
    float al = alpha[0];
    float4 a = *(const float4*)(g_acc + (size_t)row*DD + tid*4);
    float4 xv = *(const float4*)(x + (size_t)row*DD + tid*4);
    float4 v = make_float4(a.x + al*xv.x, a.y + al*xv.y, a.z + al*xv.z, a.w + al*xv.w);
    float ss = v.x*v.x + v.y*v.y + v.z*v.z + v.w*v.w;
    float total = block_reduce_sum(ss, red, tid);
    float r = rsqrtf(total * (1.0f/DD) + EPSI);
    float4 w = *(const float4*)(flnw + tid*4);
    float4 res = make_float4(v.x*r*w.x, v.y*r*w.y, v.z*r*w.z, v.w*r*w.w);
    *(float4*)(g_y + (size_t)row*DD + tid*4) = res;
}

// ---------------- launch ---------------------------------------------
extern "C" void kernel_launch(void* const* d_in, const int* in_sizes, int n_in,
                              void* d_out, int out_size) {
    const float* x    = (const float*)d_in[0];
    const float* cosT = (const float*)d_in[1];
    const float* sinT = (const float*)d_in[2];
    const float* qw   = (const float*)d_in[3];
    const float* kw   = (const float*)d_in[4];
    const float* vw   = (const float*)d_in[5];
    const float* lnw  = (const float*)d_in[6];
    const float* lam  = (const float*)d_in[7];
    const float* ow   = (const float*)d_in[8];
    const float* flnw = (const float*)d_in[9];
    const float* alpha= (const float*)d_in[10];
    float* out = (float*)d_out;

    cudaFuncSetAttribute(attn_mma, cudaFuncAttributeMaxDynamicSharedMemorySize, ATTN_SMEM);

    compute_lw<<<1, 32>>>(lam);

    for (int layer = 0; layer < NL; layer++) {
        qkv_gemm_tc<<<dim3(16, 16), 256>>>(x, qw, kw, vw, layer);
        rope_qk<<<(NQROPE + NKROPE)/256, 256>>>(cosT, sinT, layer);
        attn_mma<<<dim3(8, HH, BB), 256, ATTN_SMEM>>>(layer);
        rmsnorm_acc<<<BB*TT, 256>>>(lnw, layer);
    }

    final_norm<<<BB*TT, 256>>>(x, flnw, alpha);
    out_gemm_tc<<<dim3(16, 8), 256>>>(ow, out);
}

// round 12
// speedup vs baseline: 2.2389x; 1.0485x over previous
#include <cuda_runtime.h>
#include <math.h>
#include <cstdint>

#define BB 2
#define TT 1024
#define DD 1024
#define HH 16
#define HKV 8
#define HD 64
#define NL 3
#define MAXKV 3072
#define EPSI 1e-5f
#define NEGINF (-1e30f)

// ---------------- device scratch (static; no allocation) ----------------
__device__ float g_Q[BB*TT*DD];
__device__ float g_K[BB*MAXKV*HKV*HD];
__device__ float g_V[BB*MAXKV*HKV*HD];
__device__ float g_O[BB*TT*DD];
__device__ float g_acc[BB*TT*DD];
__device__ float g_y[BB*TT*DD];
__device__ float g_lw[NL];

// tf32-rounded copies of GEMM inputs (cp.async stages raw bits)
#define XN  (BB*TT*DD)
#define QWN (NL*DD*DD)
#define KWN (NL*(DD/2)*DD)
#define OWN (DD*DD)
__device__ float g_xr[XN];
__device__ float g_qwr[QWN];
__device__ float g_kwr[KWN];
__device__ float g_vwr[KWN];
__device__ float g_owr[OWN];

// ================= helpers ============================================
__device__ __forceinline__ uint32_t f2tf32(float x) {
    uint32_t u;
    asm("cvt.rna.tf32.f32 %0, %1;" : "=r"(u) : "f"(x));
    return u;
}
__device__ __forceinline__ float f2tf32f(float x) {
    return __uint_as_float(f2tf32(x));
}
__device__ __forceinline__ uint32_t smem_to_u32(const void* p) {
    uint32_t a;
    asm("{ .reg .u64 t; cvta.to.shared.u64 t, %1; cvt.u32.u64 %0, t; }" : "=r"(a) : "l"(p));
    return a;
}
#define CP16(dst, src) \
    asm volatile("cp.async.cg.shared.global [%0], [%1], 16;" :: "r"(dst), "l"(src))
#define CP_COMMIT() asm volatile("cp.async.commit_group;" ::: "memory")
#define CP_WAIT(n)  asm volatile("cp.async.wait_group %0;" :: "n"(n) : "memory")

__device__ __forceinline__ void mma_16n8k8(float c[4], const uint32_t a[4], const uint32_t b[2]) {
    asm volatile("mma.sync.aligned.m16n8k8.row.col.f32.tf32.tf32.f32 "
        "{%0,%1,%2,%3}, {%4,%5,%6,%7}, {%8,%9}, {%0,%1,%2,%3};"
        : "+f"(c[0]), "+f"(c[1]), "+f"(c[2]), "+f"(c[3])
        : "r"(a[0]), "r"(a[1]), "r"(a[2]), "r"(a[3]), "r"(b[0]), "r"(b[1]));
}

// ---------------- input rounding (once per launch) --------------------
__global__ void round_inputs(const float* __restrict__ x,  const float* __restrict__ qw,
                             const float* __restrict__ kw, const float* __restrict__ vw,
                             const float* __restrict__ ow) {
    int n = (blockIdx.x*blockDim.x + threadIdx.x)*4;
    const float* src; float* dst; int off;
    if      (n < XN)                  { src = x;  dst = g_xr;  off = n; }
    else if (n < XN+QWN)              { src = qw; dst = g_qwr; off = n-XN; }
    else if (n < XN+QWN+KWN)          { src = kw; dst = g_kwr; off = n-XN-QWN; }
    else if (n < XN+QWN+2*KWN)        { src = vw; dst = g_vwr; off = n-XN-QWN-KWN; }
    else                              { src = ow; dst = g_owr; off = n-XN-QWN-2*KWN; }
    float4 v = *(const float4*)(src + off);
    *(float4*)(dst + off) = make_float4(f2tf32f(v.x), f2tf32f(v.y), f2tf32f(v.z), f2tf32f(v.w));
}
#define ROUND_N4 ((XN+QWN+2*KWN+OWN)/4)

// ======================================================================
//           GEMM: cp.async double-buffered, R6 fragment layout
// ======================================================================
#define SSTRIDE 36
#define GWORDS (128*SSTRIDE)          // one tile buffer, words
#define GEMM_SMEM (2*2*GWORDS*4)      // 2 bufs x (A,W) = 73728 B

__device__ __forceinline__ void stage_ca(const float* __restrict__ A,
                                         const float* __restrict__ W,
                                         uint32_t sbase, int buf, int kt, int tid) {
    #pragma unroll
    for (int j = 0; j < 4; j++) {
        int f = tid + j*256;
        int r = f >> 3, cc = (f & 7)*4;
        uint32_t d = sbase + (uint32_t)((buf*2*GWORDS + r*SSTRIDE + cc)*4);
        CP16(d,             A + (size_t)r*DD + kt*32 + cc);
        CP16(d + GWORDS*4,  W + (size_t)r*DD + kt*32 + cc);
    }
}

__device__ __forceinline__ void compute_chunk(const uint32_t* __restrict__ As,
                                              const uint32_t* __restrict__ Ws,
                                              float c[4][4][4], int lane, int wm0, int wn0) {
    #pragma unroll
    for (int ks = 0; ks < 4; ks++) {
        int k0 = ks*8;
        uint32_t a[4][4], b[4][2];
        #pragma unroll
        for (int mi = 0; mi < 4; mi++) {
            int row = wm0 + mi*16 + (lane >> 2);
            const uint32_t* p = As + row*SSTRIDE + k0 + (lane & 3);
            a[mi][0] = p[0];
            a[mi][1] = p[8*SSTRIDE];
            a[mi][2] = p[4];
            a[mi][3] = p[8*SSTRIDE + 4];
        }
        #pragma unroll
        for (int ni = 0; ni < 4; ni++) {
            int coln = wn0 + ni*8 + (lane >> 2);
            const uint32_t* p = Ws + coln*SSTRIDE + k0 + (lane & 3);
            b[ni][0] = p[0];
            b[ni][1] = p[4];
        }
        #pragma unroll
        for (int mi = 0; mi < 4; mi++)
            #pragma unroll
            for (int ni = 0; ni < 4; ni++)
                mma_16n8k8(c[mi][ni], a[mi], b[ni]);
    }
}

__device__ __forceinline__ void tf32_mainloop(const float* __restrict__ A,
                                              const float* __restrict__ W,
                                              uint32_t* sh, float c[4][4][4],
                                              int tid, int lane, int wm0, int wn0) {
    uint32_t sbase = smem_to_u32(sh);
    stage_ca(A, W, sbase, 0, 0, tid); CP_COMMIT();
    for (int kt = 0; kt < 32; kt++) {
        int buf = kt & 1;
        if (kt < 31) { stage_ca(A, W, sbase, buf^1, kt+1, tid); CP_COMMIT(); CP_WAIT(1); }
        else         { CP_WAIT(0); }
        __syncthreads();
        compute_chunk(sh + buf*2*GWORDS, sh + buf*2*GWORDS + GWORDS, c, lane, wm0, wn0);
        __syncthreads();
    }
}

__global__ __launch_bounds__(256) void qkv_gemm_tc(int layer) {
    extern __shared__ uint32_t sh[];
    int tid = threadIdx.x, lane = tid & 31, wid = tid >> 5;
    int wm0 = (wid >> 2)*64, wn0 = (wid & 3)*32;
    int bm = blockIdx.x, bn = blockIdx.y;
    const float* A = g_xr + (size_t)bm*128*DD;
    const float* W;
    int mode, lc0;
    if (bn < 8)       { W = g_qwr + (size_t)layer*DD*DD     + (size_t)bn*128*DD;      mode = 0; lc0 = bn*128; }
    else if (bn < 12) { W = g_kwr + (size_t)layer*(DD/2)*DD + (size_t)(bn-8)*128*DD;  mode = 1; lc0 = (bn-8)*128; }
    else              { W = g_vwr + (size_t)layer*(DD/2)*DD + (size_t)(bn-12)*128*DD; mode = 2; lc0 = (bn-12)*128; }

    float c[4][4][4];
    #pragma unroll
    for (int mi = 0; mi < 4; mi++)
        #pragma unroll
        for (int ni = 0; ni < 4; ni++)
            #pragma unroll
            for (int q = 0; q < 4; q++) c[mi][ni][q] = 0.f;

    tf32_mainloop(A, W, sh, c, tid, lane, wm0, wn0);

    float* kvbase = (mode == 1) ? g_K : g_V;
    #pragma unroll
    for (int mi = 0; mi < 4; mi++) {
        #pragma unroll
        for (int half = 0; half < 2; half++) {
            int mrow = bm*128 + wm0 + mi*16 + half*8 + (lane >> 2);
            float* dst;
            if (mode == 0) {
                dst = g_Q + (size_t)mrow*DD + lc0;
            } else {
                int b = mrow >> 10, t = mrow & 1023;
                dst = kvbase + ((size_t)(b*MAXKV + layer*TT + t))*(HKV*HD) + lc0;
            }
            #pragma unroll
            for (int ni = 0; ni < 4; ni++) {
                int col = wn0 + ni*8 + (lane & 3)*2;
                float2 v = half ? make_float2(c[mi][ni][2], c[mi][ni][3])
                                : make_float2(c[mi][ni][0], c[mi][ni][1]);
                if (mode == 2) { v.x = f2tf32f(v.x); v.y = f2tf32f(v.y); }  // V: round now (attn stages raw)
                *(float2*)(dst + col) = v;
            }
        }
    }
}

__global__ __launch_bounds__(256) void out_gemm_tc(float* __restrict__ out) {
    extern __shared__ uint32_t sh[];
    int tid = threadIdx.x, lane = tid & 31, wid = tid >> 5;
    int wm0 = (wid >> 2)*64, wn0 = (wid & 3)*32;
    int bm = blockIdx.x, bn = blockIdx.y;
    const float* A = g_y + (size_t)bm*128*DD;
    const float* W = g_owr + (size_t)bn*128*DD;

    float c[4][4][4];
    #pragma unroll
    for (int mi = 0; mi < 4; mi++)
        #pragma unroll
        for (int ni = 0; ni < 4; ni++)
            #pragma unroll
            for (int q = 0; q < 4; q++) c[mi][ni][q] = 0.f;

    tf32_mainloop(A, W, sh, c, tid, lane, wm0, wn0);

    #pragma unroll
    for (int mi = 0; mi < 4; mi++) {
        #pragma unroll
        for (int half = 0; half < 2; half++) {
            int mrow = bm*128 + wm0 + mi*16 + half*8 + (lane >> 2);
            float* dst = out + (size_t)mrow*DD + bn*128;
            #pragma unroll
            for (int ni = 0; ni < 4; ni++) {
                int col = wn0 + ni*8 + (lane & 3)*2;
                float2 v = half ? make_float2(c[mi][ni][2], c[mi][ni][3])
                                : make_float2(c[mi][ni][0], c[mi][ni][1]);
                *(float2*)(dst + col) = v;
            }
        }
    }
}

// ======================================================================
//                  Flash attention on mma.sync tf32
// ======================================================================
#define ASTR 68
#define AQ_OFF 0
#define AK_OFF (128*ASTR)
#define AV_OFF (AK_OFF + 64*ASTR)
#define AP_OFF (AV_OFF + 64*ASTR)
#define ATTN_SMEM ((AP_OFF + 128*ASTR)*4)

__global__ __launch_bounds__(256) void attn_mma(int layer) {
    extern __shared__ uint32_t sm[];
    uint32_t* Qs  = sm + AQ_OFF;
    uint32_t* Ks  = sm + AK_OFF;
    uint32_t* VsT = sm + AV_OFF;
    uint32_t* Ps  = sm + AP_OFF;
    uint32_t sbase = smem_to_u32(sm);
    int tid = threadIdx.x, lane = tid & 31, wid = tid >> 5;
    int qt = blockIdx.x, h = blockIdx.y, b = blockIdx.z;
    int kh = h >> 1;
    int t0 = qt*128, m0 = wid*16;
    int q = lane >> 2, cl = lane & 3;

    // ---- stage Q (already scaled+rounded by rope_q) via cp.async ----
    #pragma unroll
    for (int j = 0; j < 8; j++) {
        int f = tid + j*256;
        int r = f >> 4, c4 = (f & 15)*4;
        CP16(sbase + (uint32_t)((AQ_OFF + r*ASTR + c4)*4),
             g_Q + ((size_t)(b*TT + t0 + r))*DD + h*HD + c4);
    }
    CP_COMMIT(); CP_WAIT(0);

    float occ[8][4];
    #pragma unroll
    for (int nt = 0; nt < 8; nt++)
        #pragma unroll
        for (int e = 0; e < 4; e++) occ[nt][e] = 0.f;
    float m0r = NEGINF, m1r = NEGINF, l0r = 0.f, l1r = 0.f;

    int ntiles = 2*qt + 2 + layer*16;
    int lim0 = t0 + m0 + q + layer*TT;
    int lim1 = lim0 + 8;

    int vkv = tid & 63, vhd0 = (tid >> 6)*16;

    for (int jt = 0; jt < ntiles; jt++) {
        __syncthreads();
        // stage K (rounded at rope_k) via cp.async
        #pragma unroll
        for (int j = 0; j < 4; j++) {
            int f = tid + j*256;
            int r = f >> 4, c4 = (f & 15)*4;
            CP16(sbase + (uint32_t)((AK_OFF + r*ASTR + c4)*4),
                 g_K + ((size_t)(b*MAXKV + jt*64 + r))*(HKV*HD) + kh*HD + c4);
        }
        CP_COMMIT();
        // stage V transposed (rounded at qkv epilogue; raw bits)
        {
            const float* vp = g_V + ((size_t)(b*MAXKV + jt*64 + vkv))*(HKV*HD) + kh*HD + vhd0;
            #pragma unroll
            for (int jj = 0; jj < 4; jj++) {
                float4 v = *(const float4*)(vp + jj*4);
                VsT[(vhd0 + jj*4 + 0)*ASTR + vkv] = __float_as_uint(v.x);
                VsT[(vhd0 + jj*4 + 1)*ASTR + vkv] = __float_as_uint(v.y);
                VsT[(vhd0 + jj*4 + 2)*ASTR + vkv] = __float_as_uint(v.z);
                VsT[(vhd0 + jj*4 + 3)*ASTR + vkv] = __float_as_uint(v.w);
            }
        }
        CP_WAIT(0);
        __syncthreads();

        // ---- S = Q · K^T ----
        float s[8][4];
        #pragma unroll
        for (int nt = 0; nt < 8; nt++) { s[nt][0]=0.f; s[nt][1]=0.f; s[nt][2]=0.f; s[nt][3]=0.f; }
        #pragma unroll
        for (int ks = 0; ks < 8; ks++) {
            uint32_t a[4];
            const uint32_t* ap = Qs + (m0 + q)*ASTR + ks*8 + cl;
            a[0] = ap[0]; a[1] = ap[8*ASTR]; a[2] = ap[4]; a[3] = ap[8*ASTR + 4];
            #pragma unroll
            for (int nt = 0; nt < 8; nt++) {
                const uint32_t* bp = Ks + (nt*8 + q)*ASTR + ks*8 + cl;
                uint32_t bb[2] = { bp[0], bp[4] };
                mma_16n8k8(s[nt], a, bb);
            }
        }

        // ---- mask + online softmax (exp2 domain; log2e folded into Q) ----
        int kbase = jt*64;
        float mx0 = NEGINF, mx1 = NEGINF;
        #pragma unroll
        for (int nt = 0; nt < 8; nt++) {
            int k0 = kbase + nt*8 + 2*cl;
            if (k0     > lim0) s[nt][0] = NEGINF;
            if (k0 + 1 > lim0) s[nt][1] = NEGINF;
            if (k0     > lim1) s[nt][2] = NEGINF;
            if (k0 + 1 > lim1) s[nt][3] = NEGINF;
            mx0 = fmaxf(mx0, fmaxf(s[nt][0], s[nt][1]));
            mx1 = fmaxf(mx1, fmaxf(s[nt][2], s[nt][3]));
        }
        mx0 = fmaxf(mx0, __shfl_xor_sync(0xffffffffu, mx0, 1));
        mx0 = fmaxf(mx0, __shfl_xor_sync(0xffffffffu, mx0, 2));
        mx1 = fmaxf(mx1, __shfl_xor_sync(0xffffffffu, mx1, 1));
        mx1 = fmaxf(mx1, __shfl_xor_sync(0xffffffffu, mx1, 2));
        float mn0 = fmaxf(m0r, mx0), mn1 = fmaxf(m1r, mx1);
        float cor0 = exp2f(m0r - mn0), cor1 = exp2f(m1r - mn1);
        m0r = mn0; m1r = mn1;
        float rs0 = 0.f, rs1 = 0.f;
        #pragma unroll
        for (int nt = 0; nt < 8; nt++) {
            s[nt][0] = exp2f(s[nt][0] - mn0); s[nt][1] = exp2f(s[nt][1] - mn0);
            s[nt][2] = exp2f(s[nt][2] - mn1); s[nt][3] = exp2f(s[nt][3] - mn1);
            rs0 += s[nt][0] + s[nt][1];
            rs1 += s[nt][2] + s[nt][3];
            uint32_t* pp = Ps + (m0 + q)*ASTR + nt*8 + 2*cl;
            *(uint2*)pp            = make_uint2(f2tf32(s[nt][0]), f2tf32(s[nt][1]));
            *(uint2*)(pp + 8*ASTR) = make_uint2(f2tf32(s[nt][2]), f2tf32(s[nt][3]));
            occ[nt][0] *= cor0; occ[nt][1] *= cor0;
            occ[nt][2] *= cor1; occ[nt][3] *= cor1;
        }
        rs0 += __shfl_xor_sync(0xffffffffu, rs0, 1);
        rs0 += __shfl_xor_sync(0xffffffffu, rs0, 2);
        rs1 += __shfl_xor_sync(0xffffffffu, rs1, 1);
        rs1 += __shfl_xor_sync(0xffffffffu, rs1, 2);
        l0r = l0r*cor0 + rs0;
        l1r = l1r*cor1 + rs1;

        // ---- O += P · V ----
        #pragma unroll
        for (int ks = 0; ks < 8; ks++) {
            uint32_t a[4];
            const uint32_t* ap = Ps + (m0 + q)*ASTR + ks*8 + cl;
            a[0] = ap[0]; a[1] = ap[8*ASTR]; a[2] = ap[4]; a[3] = ap[8*ASTR + 4];
            #pragma unroll
            for (int nt = 0; nt < 8; nt++) {
                const uint32_t* bp = VsT + (nt*8 + q)*ASTR + ks*8 + cl;
                uint32_t bb[2] = { bp[0], bp[4] };
                mma_16n8k8(occ[nt], a, bb);
            }
        }
    }

    float inv0 = 1.0f / l0r, inv1 = 1.0f / l1r;
    #pragma unroll
    for (int nt = 0; nt < 8; nt++) {
        float* d0 = g_O + ((size_t)(b*TT + t0 + m0 + q))*DD + h*HD + nt*8 + 2*cl;
        *(float2*)d0 = make_float2(occ[nt][0]*inv0, occ[nt][1]*inv0);
        *(float2*)(d0 + 8*DD) = make_float2(occ[nt][2]*inv1, occ[nt][3]*inv1);
    }
}

// ---------------- lambda weights -------------------------------------
__global__ void compute_lw(const float* __restrict__ lam) {
    if (threadIdx.x == 0) {
        float s0 = 1.f/(1.f+expf(-lam[0]));
        float s1 = 1.f/(1.f+expf(-lam[1]));
        float s2 = 1.f/(1.f+expf(-lam[2]));
        float mean = (s0+s1+s2)*(1.f/3.f);
        float d0 = s0-mean, d1 = s1-mean, d2 = s2-mean;
        float var = (d0*d0+d1*d1+d2*d2)*(1.f/3.f);
        float r = rsqrtf(var + EPSI);
        g_lw[0] = d0*r; g_lw[1] = d1*r; g_lw[2] = d2*r;
    }
}

// ---------------- fused RoPE (Q + K), outputs tf32-rounded ------------
// Q additionally pre-scaled by HD^-0.5 * log2(e) for exp2-domain softmax.
#define NQROPE (BB*TT*HH*32)
#define NKROPE (BB*TT*HKV*32)
#define QSCALE (0.125f * 1.44269504f)
__global__ void rope_qk(const float* __restrict__ cosT, const float* __restrict__ sinT, int layer) {
    int idx = blockIdx.x * blockDim.x + threadIdx.x;
    if (idx < NQROPE) {
        int d = idx & 31;
        int h = (idx >> 5) & 15;
        int t = (idx >> 9) & 1023;
        int b = idx >> 19;
        size_t base = ((size_t)(b*TT + t))*DD + h*HD + d;
        float x1 = g_Q[base], x2 = g_Q[base + 32];
        float c = cosT[t*32 + d], s = sinT[t*32 + d];
        g_Q[base]      = f2tf32f((x1*c - x2*s)*QSCALE);
        g_Q[base + 32] = f2tf32f((x2*c + x1*s)*QSCALE);
    } else {
        int k = idx - NQROPE;
        int d  = k & 31;
        int kh = (k >> 5) & 7;
        int t  = (k >> 8) & 1023;
        int b  = k >> 18;
        int p  = layer*TT + t;
        size_t base = ((size_t)(b*MAXKV + p))*(HKV*HD) + kh*HD + d;
        float x1 = g_K[base], x2 = g_K[base + 32];
        float c = cosT[p*32 + d], s = sinT[p*32 + d];
        g_K[base]      = f2tf32f(x1*c - x2*s);
        g_K[base + 32] = f2tf32f(x2*c + x1*s);
    }
}

// ---------------- row reductions -------------------------------------
__device__ __forceinline__ float block_reduce_sum(float v, float* red, int tid) {
    v += __shfl_xor_sync(0xffffffffu, v, 16);
    v += __shfl_xor_sync(0xffffffffu, v, 8);
    v += __shfl_xor_sync(0xffffffffu, v, 4);
    v += __shfl_xor_sync(0xffffffffu, v, 2);
    v += __shfl_xor_sync(0xffffffffu, v, 1);
    if ((tid & 31) == 0) red[tid >> 5] = v;
    __syncthreads();
    if (tid < 32) {
        float w = (tid < 8) ? red[tid] : 0.f;
        w += __shfl_xor_sync(0xffffffffu, w, 4);
        w += __shfl_xor_sync(0xffffffffu, w, 2);
        w += __shfl_xor_sync(0xffffffffu, w, 1);
        if (tid == 0) red[0] = w;
    }
    __syncthreads();
    return red[0];
}

__global__ __launch_bounds__(256) void rmsnorm_acc(const float* __restrict__ lnw, int layer) {
    __shared__ float red[8];
    int row = blockIdx.x, tid = threadIdx.x;
    float4 o = *(const float4*)(g_O + (size_t)row*DD + tid*4);
    float ss = o.x*o.x + o.y*o.y + o.z*o.z + o.w*o.w;
    float total = block_reduce_sum(ss, red, tid);
    float r = rsqrtf(total * (1.0f/DD) + EPSI) * g_lw[layer];
    float4 w = *(const float4*)(lnw + (size_t)layer*DD + tid*4);
    float4 res = make_float4(o.x*r*w.x, o.y*r*w.y, o.z*r*w.z, o.w*r*w.w);
    float* ap = g_acc + (size_t)row*DD + tid*4;
    if (layer == 0) {
        *(float4*)ap = res;
    } else {
        float4 a = *(const float4*)ap;
        a.x += res.x; a.y += res.y; a.z += res.z; a.w += res.w;
        *(float4*)ap = a;
    }
}

// final norm writes tf32-rounded g_y (consumed only by out_gemm via cp.async)
__global__ __launch_bounds__(256) void final_norm(const float* __restrict__ x,
                                                  const float* __restrict__ flnw,
                                                  const float* __restrict__ alpha) {
    __shared__ float red[8];
    int row = blockIdx.x, tid = threadIdx.x;
    float al = alpha[0];
    float4 a = *(const float4*)(g_acc + (size_t)row*DD + tid*4);
    float4 xv = *(const float4*)(x + (size_t)row*DD + tid*4);
    float4 v = make_float4(a.x + al*xv.x, a.y + al*xv.y, a.z + al*xv.z, a.w + al*xv.w);
    float ss = v.x*v.x + v.y*v.y + v.z*v.z + v.w*v.w;
    float total = block_reduce_sum(ss, red, tid);
    float r = rsqrtf(total * (1.0f/DD) + EPSI);
    float4 w = *(const float4*)(flnw + tid*4);
    float4 res = make_float4(f2tf32f(v.x*r*w.x), f2tf32f(v.y*r*w.y),
                             f2tf32f(v.z*r*w.z), f2tf32f(v.w*r*w.w));
    *(float4*)(g_y + (size_t)row*DD + tid*4) = res;
}

// ---------------- launch ---------------------------------------------
extern "C" void kernel_launch(void* const* d_in, const int* in_sizes, int n_in,
                              void* d_out, int out_size) {
    const float* x    = (const float*)d_in[0];
    const float* cosT = (const float*)d_in[1];
    const float* sinT = (const float*)d_in[2];
    const float* qw   = (const float*)d_in[3];
    const float* kw   = (const float*)d_in[4];
    const float* vw   = (const float*)d_in[5];
    const float* lnw  = (const float*)d_in[6];
    const float* lam  = (const float*)d_in[7];
    const float* ow   = (const float*)d_in[8];
    const float* flnw = (const float*)d_in[9];
    const float* alpha= (const float*)d_in[10];
    float* out = (float*)d_out;

    cudaFuncSetAttribute(qkv_gemm_tc, cudaFuncAttributeMaxDynamicSharedMemorySize, GEMM_SMEM);
    cudaFuncSetAttribute(out_gemm_tc, cudaFuncAttributeMaxDynamicSharedMemorySize, GEMM_SMEM);
    cudaFuncSetAttribute(attn_mma,    cudaFuncAttributeMaxDynamicSharedMemorySize, ATTN_SMEM);

    compute_lw<<<1, 32>>>(lam);
    round_inputs<<<ROUND_N4/256, 256>>>(x, qw, kw, vw, ow);

    for (int layer = 0; layer < NL; layer++) {
        qkv_gemm_tc<<<dim3(16, 16), 256, GEMM_SMEM>>>(layer);
        rope_qk<<<(NQROPE + NKROPE)/256, 256>>>(cosT, sinT, layer);
        attn_mma<<<dim3(8, HH, BB), 256, ATTN_SMEM>>>(layer);
        rmsnorm_acc<<<BB*TT, 256>>>(lnw, layer);
    }

    final_norm<<<BB*TT, 256>>>(x, flnw, alpha);
    out_gemm_tc<<<dim3(16, 8), 256, GEMM_SMEM>>>(out);
}

// round 14
// speedup vs baseline: 2.4621x; 1.0997x over previous
#include <cuda_runtime.h>
#include <math.h>
#include <cstdint>

#define BB 2
#define TT 1024
#define DD 1024
#define HH 16
#define HKV 8
#define HD 64
#define NL 3
#define MAXKV 3072
#define EPSI 1e-5f
#define NEGINF (-1e30f)

#define XN  (BB*TT*DD)
#define QWN (NL*DD*DD)
#define KWN (NL*(DD/2)*DD)
#define OWN (DD*DD)

// ---------------- device scratch (static; no allocation) ----------------
__device__ float g_Q[NL*XN];                 // roped Q, all layers
__device__ float g_K[BB*MAXKV*HKV*HD];
__device__ float g_V[BB*MAXKV*HKV*HD];
__device__ float g_O[NL*XN];                 // attention out, all layers
__device__ float g_y[XN];
__device__ float g_lw[NL];

// tf32-rounded copies of GEMM inputs (cp.async stages raw bits)
__device__ float g_xr[XN];
__device__ float g_qwr[QWN];
__device__ float g_kwr[KWN];
__device__ float g_vwr[KWN];
__device__ float g_owr[OWN];

// ================= helpers ============================================
__device__ __forceinline__ uint32_t f2tf32(float x) {
    uint32_t u;
    asm("cvt.rna.tf32.f32 %0, %1;" : "=r"(u) : "f"(x));
    return u;
}
__device__ __forceinline__ float f2tf32f(float x) {
    return __uint_as_float(f2tf32(x));
}
__device__ __forceinline__ uint32_t smem_to_u32(const void* p) {
    uint32_t a;
    asm("{ .reg .u64 t; cvta.to.shared.u64 t, %1; cvt.u32.u64 %0, t; }" : "=r"(a) : "l"(p));
    return a;
}
#define CP16(dst, src) \
    asm volatile("cp.async.cg.shared.global [%0], [%1], 16;" :: "r"(dst), "l"(src))
#define CP_COMMIT() asm volatile("cp.async.commit_group;" ::: "memory")
#define CP_WAIT(n)  asm volatile("cp.async.wait_group %0;" :: "n"(n) : "memory")

__device__ __forceinline__ void mma_16n8k8(float c[4], const uint32_t a[4], const uint32_t b[2]) {
    asm volatile("mma.sync.aligned.m16n8k8.row.col.f32.tf32.tf32.f32 "
        "{%0,%1,%2,%3}, {%4,%5,%6,%7}, {%8,%9}, {%0,%1,%2,%3};"
        : "+f"(c[0]), "+f"(c[1]), "+f"(c[2]), "+f"(c[3])
        : "r"(a[0]), "r"(a[1]), "r"(a[2]), "r"(a[3]), "r"(b[0]), "r"(b[1]));
}

// ---------------- input rounding (once per launch) --------------------
__global__ void round_inputs(const float* __restrict__ x,  const float* __restrict__ qw,
                             const float* __restrict__ kw, const float* __restrict__ vw,
                             const float* __restrict__ ow) {
    int n = (blockIdx.x*blockDim.x + threadIdx.x)*4;
    const float* src; float* dst; int off;
    if      (n < XN)                  { src = x;  dst = g_xr;  off = n; }
    else if (n < XN+QWN)              { src = qw; dst = g_qwr; off = n-XN; }
    else if (n < XN+QWN+KWN)          { src = kw; dst = g_kwr; off = n-XN-QWN; }
    else if (n < XN+QWN+2*KWN)        { src = vw; dst = g_vwr; off = n-XN-QWN-KWN; }
    else                              { src = ow; dst = g_owr; off = n-XN-QWN-2*KWN; }
    float4 v = *(const float4*)(src + off);
    *(float4*)(dst + off) = make_float4(f2tf32f(v.x), f2tf32f(v.y), f2tf32f(v.z), f2tf32f(v.w));
}
#define ROUND_N4 ((XN+QWN+2*KWN+OWN)/4)

// ======================================================================
//           GEMM: cp.async double-buffered, all layers in one grid
// ======================================================================
#define SSTRIDE 36
#define GWORDS (128*SSTRIDE)
#define GEMM_SMEM (2*2*GWORDS*4)

__device__ __forceinline__ void stage_ca(const float* __restrict__ A,
                                         const float* __restrict__ W,
                                         uint32_t sbase, int buf, int kt, int tid) {
    #pragma unroll
    for (int j = 0; j < 4; j++) {
        int f = tid + j*256;
        int r = f >> 3, cc = (f & 7)*4;
        uint32_t d = sbase + (uint32_t)((buf*2*GWORDS + r*SSTRIDE + cc)*4);
        CP16(d,             A + (size_t)r*DD + kt*32 + cc);
        CP16(d + GWORDS*4,  W + (size_t)r*DD + kt*32 + cc);
    }
}

__device__ __forceinline__ void compute_chunk(const uint32_t* __restrict__ As,
                                              const uint32_t* __restrict__ Ws,
                                              float c[4][4][4], int lane, int wm0, int wn0) {
    #pragma unroll
    for (int ks = 0; ks < 4; ks++) {
        int k0 = ks*8;
        uint32_t a[4][4], b[4][2];
        #pragma unroll
        for (int mi = 0; mi < 4; mi++) {
            int row = wm0 + mi*16 + (lane >> 2);
            const uint32_t* p = As + row*SSTRIDE + k0 + (lane & 3);
            a[mi][0] = p[0];
            a[mi][1] = p[8*SSTRIDE];
            a[mi][2] = p[4];
            a[mi][3] = p[8*SSTRIDE + 4];
        }
        #pragma unroll
        for (int ni = 0; ni < 4; ni++) {
            int coln = wn0 + ni*8 + (lane >> 2);
            const uint32_t* p = Ws + coln*SSTRIDE + k0 + (lane & 3);
            b[ni][0] = p[0];
            b[ni][1] = p[4];
        }
        #pragma unroll
        for (int mi = 0; mi < 4; mi++)
            #pragma unroll
            for (int ni = 0; ni < 4; ni++)
                mma_16n8k8(c[mi][ni], a[mi], b[ni]);
    }
}

__device__ __forceinline__ void tf32_mainloop(const float* __restrict__ A,
                                              const float* __restrict__ W,
                                              uint32_t* sh, float c[4][4][4],
                                              int tid, int lane, int wm0, int wn0) {
    uint32_t sbase = smem_to_u32(sh);
    stage_ca(A, W, sbase, 0, 0, tid); CP_COMMIT();
    for (int kt = 0; kt < 32; kt++) {
        int buf = kt & 1;
        if (kt < 31) { stage_ca(A, W, sbase, buf^1, kt+1, tid); CP_COMMIT(); CP_WAIT(1); }
        else         { CP_WAIT(0); }
        __syncthreads();
        compute_chunk(sh + buf*2*GWORDS, sh + buf*2*GWORDS + GWORDS, c, lane, wm0, wn0);
        __syncthreads();
    }
}

// grid (16, 16, NL): bm, bn(virtual Q/K/V cols), layer
__global__ __launch_bounds__(256) void qkv_gemm_tc() {
    extern __shared__ uint32_t sh[];
    int tid = threadIdx.x, lane = tid & 31, wid = tid >> 5;
    int wm0 = (wid >> 2)*64, wn0 = (wid & 3)*32;
    int bm = blockIdx.x, bn = blockIdx.y, layer = blockIdx.z;
    const float* A = g_xr + (size_t)bm*128*DD;
    const float* W;
    int mode, lc0;
    if (bn < 8)       { W = g_qwr + (size_t)layer*DD*DD     + (size_t)bn*128*DD;      mode = 0; lc0 = bn*128; }
    else if (bn < 12) { W = g_kwr + (size_t)layer*(DD/2)*DD + (size_t)(bn-8)*128*DD;  mode = 1; lc0 = (bn-8)*128; }
    else              { W = g_vwr + (size_t)layer*(DD/2)*DD + (size_t)(bn-12)*128*DD; mode = 2; lc0 = (bn-12)*128; }

    float c[4][4][4];
    #pragma unroll
    for (int mi = 0; mi < 4; mi++)
        #pragma unroll
        for (int ni = 0; ni < 4; ni++)
            #pragma unroll
            for (int q = 0; q < 4; q++) c[mi][ni][q] = 0.f;

    tf32_mainloop(A, W, sh, c, tid, lane, wm0, wn0);

    float* kvbase = (mode == 1) ? g_K : g_V;
    #pragma unroll
    for (int mi = 0; mi < 4; mi++) {
        #pragma unroll
        for (int half = 0; half < 2; half++) {
            int mrow = bm*128 + wm0 + mi*16 + half*8 + (lane >> 2);
            float* dst;
            if (mode == 0) {
                dst = g_Q + (size_t)layer*XN + (size_t)mrow*DD + lc0;
            } else {
                int b = mrow >> 10, t = mrow & 1023;
                dst = kvbase + ((size_t)(b*MAXKV + layer*TT + t))*(HKV*HD) + lc0;
            }
            #pragma unroll
            for (int ni = 0; ni < 4; ni++) {
                int col = wn0 + ni*8 + (lane & 3)*2;
                float2 v = half ? make_float2(c[mi][ni][2], c[mi][ni][3])
                                : make_float2(c[mi][ni][0], c[mi][ni][1]);
                if (mode == 2) { v.x = f2tf32f(v.x); v.y = f2tf32f(v.y); }
                *(float2*)(dst + col) = v;
            }
        }
    }
}

__global__ __launch_bounds__(256) void out_gemm_tc(float* __restrict__ out) {
    extern __shared__ uint32_t sh[];
    int tid = threadIdx.x, lane = tid & 31, wid = tid >> 5;
    int wm0 = (wid >> 2)*64, wn0 = (wid & 3)*32;
    int bm = blockIdx.x, bn = blockIdx.y;
    const float* A = g_y + (size_t)bm*128*DD;
    const float* W = g_owr + (size_t)bn*128*DD;

    float c[4][4][4];
    #pragma unroll
    for (int mi = 0; mi < 4; mi++)
        #pragma unroll
        for (int ni = 0; ni < 4; ni++)
            #pragma unroll
            for (int q = 0; q < 4; q++) c[mi][ni][q] = 0.f;

    tf32_mainloop(A, W, sh, c, tid, lane, wm0, wn0);

    #pragma unroll
    for (int mi = 0; mi < 4; mi++) {
        #pragma unroll
        for (int half = 0; half < 2; half++) {
            int mrow = bm*128 + wm0 + mi*16 + half*8 + (lane >> 2);
            float* dst = out + (size_t)mrow*DD + bn*128;
            #pragma unroll
            for (int ni = 0; ni < 4; ni++) {
                int col = wn0 + ni*8 + (lane & 3)*2;
                float2 v = half ? make_float2(c[mi][ni][2], c[mi][ni][3])
                                : make_float2(c[mi][ni][0], c[mi][ni][1]);
                *(float2*)(dst + col) = v;
            }
        }
    }
}

// ======================================================================
//          Flash attention, all layers in one grid (8, 16, BB*NL)
// ======================================================================
#define ASTR 68
#define AQ_OFF 0
#define AK_OFF (128*ASTR)
#define AV_OFF (AK_OFF + 64*ASTR)
#define AP_OFF (AV_OFF + 64*ASTR)
#define ATTN_SMEM ((AP_OFF + 128*ASTR)*4)

__global__ __launch_bounds__(256) void attn_mma() {
    extern __shared__ uint32_t sm[];
    uint32_t* Qs  = sm + AQ_OFF;
    uint32_t* Ks  = sm + AK_OFF;
    uint32_t* VsT = sm + AV_OFF;
    uint32_t* Ps  = sm + AP_OFF;
    uint32_t sbase = smem_to_u32(sm);
    int tid = threadIdx.x, lane = tid & 31, wid = tid >> 5;
    int qt = blockIdx.x, h = blockIdx.y;
    int z = blockIdx.z;
    int layer = z % NL, b = z / NL;
    int kh = h >> 1;
    int t0 = qt*128, m0 = wid*16;
    int q = lane >> 2, cl = lane & 3;
    const float* Qsrc = g_Q + (size_t)layer*XN;
    float* Odst = g_O + (size_t)layer*XN;

    #pragma unroll
    for (int j = 0; j < 8; j++) {
        int f = tid + j*256;
        int r = f >> 4, c4 = (f & 15)*4;
        CP16(sbase + (uint32_t)((AQ_OFF + r*ASTR + c4)*4),
             Qsrc + ((size_t)(b*TT + t0 + r))*DD + h*HD + c4);
    }
    CP_COMMIT(); CP_WAIT(0);

    float occ[8][4];
    #pragma unroll
    for (int nt = 0; nt < 8; nt++)
        #pragma unroll
        for (int e = 0; e < 4; e++) occ[nt][e] = 0.f;
    float m0r = NEGINF, m1r = NEGINF, l0r = 0.f, l1r = 0.f;

    int ntiles = 2*qt + 2 + layer*16;
    int lim0 = t0 + m0 + q + layer*TT;
    int lim1 = lim0 + 8;

    int vkv = tid & 63, vhd0 = (tid >> 6)*16;

    for (int jt = 0; jt < ntiles; jt++) {
        __syncthreads();
        #pragma unroll
        for (int j = 0; j < 4; j++) {
            int f = tid + j*256;
            int r = f >> 4, c4 = (f & 15)*4;
            CP16(sbase + (uint32_t)((AK_OFF + r*ASTR + c4)*4),
                 g_K + ((size_t)(b*MAXKV + jt*64 + r))*(HKV*HD) + kh*HD + c4);
        }
        CP_COMMIT();
        {
            const float* vp = g_V + ((size_t)(b*MAXKV + jt*64 + vkv))*(HKV*HD) + kh*HD + vhd0;
            #pragma unroll
            for (int jj = 0; jj < 4; jj++) {
                float4 v = *(const float4*)(vp + jj*4);
                VsT[(vhd0 + jj*4 + 0)*ASTR + vkv] = __float_as_uint(v.x);
                VsT[(vhd0 + jj*4 + 1)*ASTR + vkv] = __float_as_uint(v.y);
                VsT[(vhd0 + jj*4 + 2)*ASTR + vkv] = __float_as_uint(v.z);
                VsT[(vhd0 + jj*4 + 3)*ASTR + vkv] = __float_as_uint(v.w);
            }
        }
        CP_WAIT(0);
        __syncthreads();

        // ---- S = Q · K^T ----
        float s[8][4];
        #pragma unroll
        for (int nt = 0; nt < 8; nt++) { s[nt][0]=0.f; s[nt][1]=0.f; s[nt][2]=0.f; s[nt][3]=0.f; }
        #pragma unroll
        for (int ks = 0; ks < 8; ks++) {
            uint32_t a[4];
            const uint32_t* ap = Qs + (m0 + q)*ASTR + ks*8 + cl;
            a[0] = ap[0]; a[1] = ap[8*ASTR]; a[2] = ap[4]; a[3] = ap[8*ASTR + 4];
            #pragma unroll
            for (int nt = 0; nt < 8; nt++) {
                const uint32_t* bp = Ks + (nt*8 + q)*ASTR + ks*8 + cl;
                uint32_t bb[2] = { bp[0], bp[4] };
                mma_16n8k8(s[nt], a, bb);
            }
        }

        // ---- mask + online softmax (exp2 domain) ----
        int kbase = jt*64;
        float mx0 = NEGINF, mx1 = NEGINF;
        #pragma unroll
        for (int nt = 0; nt < 8; nt++) {
            int k0 = kbase + nt*8 + 2*cl;
            if (k0     > lim0) s[nt][0] = NEGINF;
            if (k0 + 1 > lim0) s[nt][1] = NEGINF;
            if (k0     > lim1) s[nt][2] = NEGINF;
            if (k0 + 1 > lim1) s[nt][3] = NEGINF;
            mx0 = fmaxf(mx0, fmaxf(s[nt][0], s[nt][1]));
            mx1 = fmaxf(mx1, fmaxf(s[nt][2], s[nt][3]));
        }
        mx0 = fmaxf(mx0, __shfl_xor_sync(0xffffffffu, mx0, 1));
        mx0 = fmaxf(mx0, __shfl_xor_sync(0xffffffffu, mx0, 2));
        mx1 = fmaxf(mx1, __shfl_xor_sync(0xffffffffu, mx1, 1));
        mx1 = fmaxf(mx1, __shfl_xor_sync(0xffffffffu, mx1, 2));
        float mn0 = fmaxf(m0r, mx0), mn1 = fmaxf(m1r, mx1);
        float cor0 = exp2f(m0r - mn0), cor1 = exp2f(m1r - mn1);
        m0r = mn0; m1r = mn1;
        float rs0 = 0.f, rs1 = 0.f;
        #pragma unroll
        for (int nt = 0; nt < 8; nt++) {
            s[nt][0] = exp2f(s[nt][0] - mn0); s[nt][1] = exp2f(s[nt][1] - mn0);
            s[nt][2] = exp2f(s[nt][2] - mn1); s[nt][3] = exp2f(s[nt][3] - mn1);
            rs0 += s[nt][0] + s[nt][1];
            rs1 += s[nt][2] + s[nt][3];
            uint32_t* pp = Ps + (m0 + q)*ASTR + nt*8 + 2*cl;
            *(uint2*)pp            = make_uint2(f2tf32(s[nt][0]), f2tf32(s[nt][1]));
            *(uint2*)(pp + 8*ASTR) = make_uint2(f2tf32(s[nt][2]), f2tf32(s[nt][3]));
            occ[nt][0] *= cor0; occ[nt][1] *= cor0;
            occ[nt][2] *= cor1; occ[nt][3] *= cor1;
        }
        rs0 += __shfl_xor_sync(0xffffffffu, rs0, 1);
        rs0 += __shfl_xor_sync(0xffffffffu, rs0, 2);
        rs1 += __shfl_xor_sync(0xffffffffu, rs1, 1);
        rs1 += __shfl_xor_sync(0xffffffffu, rs1, 2);
        l0r = l0r*cor0 + rs0;
        l1r = l1r*cor1 + rs1;

        // ---- O += P · V ----
        #pragma unroll
        for (int ks = 0; ks < 8; ks++) {
            uint32_t a[4];
            const uint32_t* ap = Ps + (m0 + q)*ASTR + ks*8 + cl;
            a[0] = ap[0]; a[1] = ap[8*ASTR]; a[2] = ap[4]; a[3] = ap[8*ASTR + 4];
            #pragma unroll
            for (int nt = 0; nt < 8; nt++) {
                const uint32_t* bp = VsT + (nt*8 + q)*ASTR + ks*8 + cl;
                uint32_t bb[2] = { bp[0], bp[4] };
                mma_16n8k8(occ[nt], a, bb);
            }
        }
    }

    float inv0 = 1.0f / l0r, inv1 = 1.0f / l1r;
    #pragma unroll
    for (int nt = 0; nt < 8; nt++) {
        float* d0 = Odst + ((size_t)(b*TT + t0 + m0 + q))*DD + h*HD + nt*8 + 2*cl;
        *(float2*)d0 = make_float2(occ[nt][0]*inv0, occ[nt][1]*inv0);
        *(float2*)(d0 + 8*DD) = make_float2(occ[nt][2]*inv1, occ[nt][3]*inv1);
    }
}

// ---------------- lambda weights -------------------------------------
__global__ void compute_lw(const float* __restrict__ lam) {
    if (threadIdx.x == 0) {
        float s0 = 1.f/(1.f+expf(-lam[0]));
        float s1 = 1.f/(1.f+expf(-lam[1]));
        float s2 = 1.f/(1.f+expf(-lam[2]));
        float mean = (s0+s1+s2)*(1.f/3.f);
        float d0 = s0-mean, d1 = s1-mean, d2 = s2-mean;
        float var = (d0*d0+d1*d1+d2*d2)*(1.f/3.f);
        float r = rsqrtf(var + EPSI);
        g_lw[0] = d0*r; g_lw[1] = d1*r; g_lw[2] = d2*r;
    }
}

// ---------------- RoPE, all layers in one launch ----------------------
#define NQROPE (BB*TT*HH*32)      // 2^20 per layer
#define NKROPE (BB*TT*HKV*32)     // 2^19 per layer
#define QSCALE (0.125f * 1.44269504f)
__global__ void rope_all(const float* __restrict__ cosT, const float* __restrict__ sinT) {
    int idx = blockIdx.x * blockDim.x + threadIdx.x;
    if (idx < NL*NQROPE) {
        int layer = idx >> 20;
        int r = idx & (NQROPE-1);
        int d = r & 31;
        int h = (r >> 5) & 15;
        int t = (r >> 9) & 1023;
        int b = r >> 19;
        size_t base = (size_t)layer*XN + ((size_t)(b*TT + t))*DD + h*HD + d;
        float x1 = g_Q[base], x2 = g_Q[base + 32];
        float c = cosT[t*32 + d], s = sinT[t*32 + d];
        g_Q[base]      = f2tf32f((x1*c - x2*s)*QSCALE);
        g_Q[base + 32] = f2tf32f((x2*c + x1*s)*QSCALE);
    } else {
        int j = idx - NL*NQROPE;
        int layer = j >> 19;
        int k = j & (NKROPE-1);
        int d  = k & 31;
        int kh = (k >> 5) & 7;
        int t  = (k >> 8) & 1023;
        int b  = k >> 18;
        int p  = layer*TT + t;
        size_t base = ((size_t)(b*MAXKV + p))*(HKV*HD) + kh*HD + d;
        float x1 = g_K[base], x2 = g_K[base + 32];
        float c = cosT[p*32 + d], s = sinT[p*32 + d];
        g_K[base]      = f2tf32f(x1*c - x2*s);
        g_K[base + 32] = f2tf32f(x2*c + x1*s);
    }
}
#define ROPE_THREADS (NL*(NQROPE + NKROPE))

// ---------------- fused 3x rmsnorm + residual + final norm ------------
__device__ __forceinline__ float block_reduce_sum(float v, float* red, int tid) {
    v += __shfl_xor_sync(0xffffffffu, v, 16);
    v += __shfl_xor_sync(0xffffffffu, v, 8);
    v += __shfl_xor_sync(0xffffffffu, v, 4);
    v += __shfl_xor_sync(0xffffffffu, v, 2);
    v += __shfl_xor_sync(0xffffffffu, v, 1);
    if ((tid & 31) == 0) red[tid >> 5] = v;
    __syncthreads();
    if (tid < 32) {
        float w = (tid < 8) ? red[tid] : 0.f;
        w += __shfl_xor_sync(0xffffffffu, w, 4);
        w += __shfl_xor_sync(0xffffffffu, w, 2);
        w += __shfl_xor_sync(0xffffffffu, w, 1);
        if (tid == 0) red[0] = w;
    }
    __syncthreads();
    return red[0];
}

__global__ __launch_bounds__(256) void acc_final(const float* __restrict__ x,
                                                 const float* __restrict__ lnw,
                                                 const float* __restrict__ flnw,
                                                 const float* __restrict__ alpha) {
    __shared__ float red[4][8];
    int row = blockIdx.x, tid = threadIdx.x;
    float4 o0 = *(const float4*)(g_O + 0*(size_t)XN + (size_t)row*DD + tid*4);
    float4 o1 = *(const float4*)(g_O + 1*(size_t)XN + (size_t)row*DD + tid*4);
    float4 o2 = *(const float4*)(g_O + 2*(size_t)XN + (size_t)row*DD + tid*4);
    float ss0 = o0.x*o0.x + o0.y*o0.y + o0.z*o0.z + o0.w*o0.w;
    float ss1 = o1.x*o1.x + o1.y*o1.y + o1.z*o1.z + o1.w*o1.w;
    float ss2 = o2.x*o2.x + o2.y*o2.y + o2.z*o2.z + o2.w*o2.w;
    float r0 = rsqrtf(block_reduce_sum(ss0, red[0], tid) * (1.0f/DD) + EPSI) * g_lw[0];
    float r1 = rsqrtf(block_reduce_sum(ss1, red[1], tid) * (1.0f/DD) + EPSI) * g_lw[1];
    float r2 = rsqrtf(block_reduce_sum(ss2, red[2], tid) * (1.0f/DD) + EPSI) * g_lw[2];
    float4 w0 = *(const float4*)(lnw + 0*DD + tid*4);
    float4 w1 = *(const float4*)(lnw + 1*DD + tid*4);
    float4 w2 = *(const float4*)(lnw + 2*DD + tid*4);
    float al = alpha[0];
    float4 xv = *(const float4*)(x + (size_t)row*DD + tid*4);
    float4 v;
    v.x = o0.x*r0*w0.x + o1.x*r1*w1.x + o2.x*r2*w2.x + al*xv.x;
    v.y = o0.y*r0*w0.y + o1.y*r1*w1.y + o2.y*r2*w2.y + al*xv.y;
    v.z = o0.z*r0*w0.z + o1.z*r1*w1.z + o2.z*r2*w2.z + al*xv.z;
    v.w = o0.w*r0*w0.w + o1.w*r1*w1.w + o2.w*r2*w2.w + al*xv.w;
    float ss = v.x*v.x + v.y*v.y + v.z*v.z + v.w*v.w;
    float r = rsqrtf(block_reduce_sum(ss, red[3], tid) * (1.0f/DD) + EPSI);
    float4 fw = *(const float4*)(flnw + tid*4);
    float4 res = make_float4(f2tf32f(v.x*r*fw.x), f2tf32f(v.y*r*fw.y),
                             f2tf32f(v.z*r*fw.z), f2tf32f(v.w*r*fw.w));
    *(float4*)(g_y + (size_t)row*DD + tid*4) = res;
}

// ---------------- launch ---------------------------------------------
extern "C" void kernel_launch(void* const* d_in, const int* in_sizes, int n_in,
                              void* d_out, int out_size) {
    const float* x    = (const float*)d_in[0];
    const float* cosT = (const float*)d_in[1];
    const float* sinT = (const float*)d_in[2];
    const float* lnw  = (const float*)d_in[6];
    const float* lam  = (const float*)d_in[7];
    const float* flnw = (const float*)d_in[9];
    const float* alpha= (const float*)d_in[10];
    float* out = (float*)d_out;

    cudaFuncSetAttribute(qkv_gemm_tc, cudaFuncAttributeMaxDynamicSharedMemorySize, GEMM_SMEM);
    cudaFuncSetAttribute(out_gemm_tc, cudaFuncAttributeMaxDynamicSharedMemorySize, GEMM_SMEM);
    cudaFuncSetAttribute(attn_mma,    cudaFuncAttributeMaxDynamicSharedMemorySize, ATTN_SMEM);

    compute_lw<<<1, 32>>>(lam);
    round_inputs<<<ROUND_N4/256, 256>>>(x, (const float*)d_in[3], (const float*)d_in[4],
                                        (const float*)d_in[5], (const float*)d_in[8]);

    qkv_gemm_tc<<<dim3(16, 16, NL), 256, GEMM_SMEM>>>();
    rope_all<<<ROPE_THREADS/256, 256>>>(cosT, sinT);
    attn_mma<<<dim3(8, HH, BB*NL), 256, ATTN_SMEM>>>();
    acc_final<<<BB*TT, 256>>>(x, lnw, flnw, alpha);
    out_gemm_tc<<<dim3(16, 8), 256, GEMM_SMEM>>>(out);
}

// round 16
// speedup vs baseline: 4.3309x; 1.7590x over previous
#include <cuda_runtime.h>
#include <cuda_fp16.h>
#include <math.h>
#include <cstdint>

#define BB 2
#define TT 1024
#define DD 1024
#define HH 16
#define HKV 8
#define HD 64
#define NL 3
#define MAXKV 3072
#define EPSI 1e-5f
#define NEGINF (-1e30f)

#define XN  (BB*TT*DD)
#define QWN (NL*DD*DD)
#define KWN (NL*(DD/2)*DD)
#define OWN (DD*DD)

// ---------------- device scratch (static; no allocation) ----------------
__device__ __half g_Q[NL*XN];                // roped Q (half), all layers
__device__ __half g_K[BB*MAXKV*HKV*HD];      // roped K cache (half)
__device__ __half g_V[BB*MAXKV*HKV*HD];      // V cache (half)
__device__ float  g_O[NL*XN];                // attention out (fp32)
__device__ __half g_y[XN];                   // pre-outproj (half)
__device__ float  g_lw[NL];

// half copies of GEMM inputs (cp.async stages raw bits)
__device__ __half g_xh[XN];
__device__ __half g_qwh[QWN];
__device__ __half g_kwh[KWN];
__device__ __half g_vwh[KWN];
__device__ __half g_owh[OWN];

// ================= helpers ============================================
__device__ __forceinline__ uint32_t smem_to_u32(const void* p) {
    uint32_t a;
    asm("{ .reg .u64 t; cvta.to.shared.u64 t, %1; cvt.u32.u64 %0, t; }" : "=r"(a) : "l"(p));
    return a;
}
#define CP16(dst, src) \
    asm volatile("cp.async.cg.shared.global [%0], [%1], 16;" :: "r"(dst), "l"(src))
#define CP_COMMIT() asm volatile("cp.async.commit_group;" ::: "memory")
#define CP_WAIT(n)  asm volatile("cp.async.wait_group %0;" :: "n"(n) : "memory")

__device__ __forceinline__ void mma_16n8k16(float c[4], const uint32_t a[4], const uint32_t b[2]) {
    asm volatile("mma.sync.aligned.m16n8k16.row.col.f32.f16.f16.f32 "
        "{%0,%1,%2,%3}, {%4,%5,%6,%7}, {%8,%9}, {%0,%1,%2,%3};"
        : "+f"(c[0]), "+f"(c[1]), "+f"(c[2]), "+f"(c[3])
        : "r"(a[0]), "r"(a[1]), "r"(a[2]), "r"(a[3]), "r"(b[0]), "r"(b[1]));
}
__device__ __forceinline__ uint32_t packh2(float lo, float hi) {
    __half2 h = __floats2half2_rn(lo, hi);
    return *(uint32_t*)&h;
}

// ---------------- input conversion (once per launch) ------------------
__global__ void convert_inputs(const float* __restrict__ x,  const float* __restrict__ qw,
                               const float* __restrict__ kw, const float* __restrict__ vw,
                               const float* __restrict__ ow) {
    int n = (blockIdx.x*blockDim.x + threadIdx.x)*8;
    const float* src; __half* dst; int off;
    if      (n < XN)                  { src = x;  dst = g_xh;  off = n; }
    else if (n < XN+QWN)              { src = qw; dst = g_qwh; off = n-XN; }
    else if (n < XN+QWN+KWN)          { src = kw; dst = g_kwh; off = n-XN-QWN; }
    else if (n < XN+QWN+2*KWN)        { src = vw; dst = g_vwh; off = n-XN-QWN-KWN; }
    else                              { src = ow; dst = g_owh; off = n-XN-QWN-2*KWN; }
    float4 v0 = *(const float4*)(src + off);
    float4 v1 = *(const float4*)(src + off + 4);
    uint4 u;
    u.x = packh2(v0.x, v0.y); u.y = packh2(v0.z, v0.w);
    u.z = packh2(v1.x, v1.y); u.w = packh2(v1.z, v1.w);
    *(uint4*)(dst + off) = u;
}
#define CONV_BLOCKS ((XN+QWN+2*KWN+OWN)/8/256)

// ======================================================================
//      GEMM: fp16 m16n8k16, cp.async double-buffered, K-chunk 64
// ======================================================================
#define SSTRIDE 36                    // words per row (32 used + 4 pad)
#define GWORDS (128*SSTRIDE)          // 4608 words per tile buffer
#define GEMM_SMEM (2*2*GWORDS*4)      // 73728 B

__device__ __forceinline__ void stage_ca(const __half* __restrict__ A,
                                         const __half* __restrict__ W,
                                         uint32_t sbase, int buf, int kt, int tid) {
    #pragma unroll
    for (int j = 0; j < 4; j++) {
        int f = tid + j*256;          // 0..1023
        int r = f >> 3, seg = f & 7;  // row, 16B segment (8 halves)
        uint32_t d = sbase + (uint32_t)((buf*2*GWORDS + r*SSTRIDE + seg*4)*4);
        CP16(d,             A + (size_t)r*DD + kt*64 + seg*8);
        CP16(d + GWORDS*4,  W + (size_t)r*DD + kt*64 + seg*8);
    }
}

__device__ __forceinline__ void compute_chunk(const uint32_t* __restrict__ As,
                                              const uint32_t* __restrict__ Ws,
                                              float c[4][4][4], int lane, int wm0, int wn0) {
    int q = lane >> 2, cl = lane & 3;
    #pragma unroll
    for (int ks = 0; ks < 4; ks++) {      // 4 x k16 per 64-chunk
        int k0 = ks*8;
        uint32_t a[4][4], b[4][2];
        #pragma unroll
        for (int mi = 0; mi < 4; mi++) {
            int row = wm0 + mi*16 + q;
            const uint32_t* p = As + row*SSTRIDE + k0 + cl;
            a[mi][0] = p[0];
            a[mi][1] = p[8*SSTRIDE];
            a[mi][2] = p[4];
            a[mi][3] = p[8*SSTRIDE + 4];
        }
        #pragma unroll
        for (int ni = 0; ni < 4; ni++) {
            int coln = wn0 + ni*8 + q;
            const uint32_t* p = Ws + coln*SSTRIDE + k0 + cl;
            b[ni][0] = p[0];
            b[ni][1] = p[4];
        }
        #pragma unroll
        for (int mi = 0; mi < 4; mi++)
            #pragma unroll
            for (int ni = 0; ni < 4; ni++)
                mma_16n8k16(c[mi][ni], a[mi], b[ni]);
    }
}

__device__ __forceinline__ void h16_mainloop(const __half* __restrict__ A,
                                             const __half* __restrict__ W,
                                             uint32_t* sh, float c[4][4][4],
                                             int tid, int lane, int wm0, int wn0) {
    uint32_t sbase = smem_to_u32(sh);
    stage_ca(A, W, sbase, 0, 0, tid); CP_COMMIT();
    for (int kt = 0; kt < 16; kt++) {
        int buf = kt & 1;
        if (kt < 15) { stage_ca(A, W, sbase, buf^1, kt+1, tid); CP_COMMIT(); CP_WAIT(1); }
        else         { CP_WAIT(0); }
        __syncthreads();
        compute_chunk(sh + buf*2*GWORDS, sh + buf*2*GWORDS + GWORDS, c, lane, wm0, wn0);
        __syncthreads();
    }
}

// grid (16, 16, NL)
__global__ __launch_bounds__(256) void qkv_gemm_tc() {
    extern __shared__ uint32_t sh[];
    int tid = threadIdx.x, lane = tid & 31, wid = tid >> 5;
    int wm0 = (wid >> 2)*64, wn0 = (wid & 3)*32;
    int bm = blockIdx.x, bn = blockIdx.y, layer = blockIdx.z;
    const __half* A = g_xh + (size_t)bm*128*DD;
    const __half* W;
    int mode, lc0;
    if (bn < 8)       { W = g_qwh + (size_t)layer*DD*DD     + (size_t)bn*128*DD;      mode = 0; lc0 = bn*128; }
    else if (bn < 12) { W = g_kwh + (size_t)layer*(DD/2)*DD + (size_t)(bn-8)*128*DD;  mode = 1; lc0 = (bn-8)*128; }
    else              { W = g_vwh + (size_t)layer*(DD/2)*DD + (size_t)(bn-12)*128*DD; mode = 2; lc0 = (bn-12)*128; }

    float c[4][4][4];
    #pragma unroll
    for (int mi = 0; mi < 4; mi++)
        #pragma unroll
        for (int ni = 0; ni < 4; ni++)
            #pragma unroll
            for (int q = 0; q < 4; q++) c[mi][ni][q] = 0.f;

    h16_mainloop(A, W, sh, c, tid, lane, wm0, wn0);

    __half* kvbase = (mode == 1) ? g_K : g_V;
    #pragma unroll
    for (int mi = 0; mi < 4; mi++) {
        #pragma unroll
        for (int half = 0; half < 2; half++) {
            int mrow = bm*128 + wm0 + mi*16 + half*8 + (lane >> 2);
            __half* dst;
            if (mode == 0) {
                dst = g_Q + (size_t)layer*XN + (size_t)mrow*DD + lc0;
            } else {
                int b = mrow >> 10, t = mrow & 1023;
                dst = kvbase + ((size_t)(b*MAXKV + layer*TT + t))*(HKV*HD) + lc0;
            }
            #pragma unroll
            for (int ni = 0; ni < 4; ni++) {
                int col = wn0 + ni*8 + (lane & 3)*2;
                uint32_t v = half ? packh2(c[mi][ni][2], c[mi][ni][3])
                                  : packh2(c[mi][ni][0], c[mi][ni][1]);
                *(uint32_t*)(dst + col) = v;
            }
        }
    }
}

__global__ __launch_bounds__(256) void out_gemm_tc(float* __restrict__ out) {
    extern __shared__ uint32_t sh[];
    int tid = threadIdx.x, lane = tid & 31, wid = tid >> 5;
    int wm0 = (wid >> 2)*64, wn0 = (wid & 3)*32;
    int bm = blockIdx.x, bn = blockIdx.y;
    const __half* A = g_y + (size_t)bm*128*DD;
    const __half* W = g_owh + (size_t)bn*128*DD;

    float c[4][4][4];
    #pragma unroll
    for (int mi = 0; mi < 4; mi++)
        #pragma unroll
        for (int ni = 0; ni < 4; ni++)
            #pragma unroll
            for (int q = 0; q < 4; q++) c[mi][ni][q] = 0.f;

    h16_mainloop(A, W, sh, c, tid, lane, wm0, wn0);

    #pragma unroll
    for (int mi = 0; mi < 4; mi++) {
        #pragma unroll
        for (int half = 0; half < 2; half++) {
            int mrow = bm*128 + wm0 + mi*16 + half*8 + (lane >> 2);
            float* dst = out + (size_t)mrow*DD + bn*128;
            #pragma unroll
            for (int ni = 0; ni < 4; ni++) {
                int col = wn0 + ni*8 + (lane & 3)*2;
                float2 v = half ? make_float2(c[mi][ni][2], c[mi][ni][3])
                                : make_float2(c[mi][ni][0], c[mi][ni][1]);
                *(float2*)(dst + col) = v;
            }
        }
    }
}

// ======================================================================
//        Flash attention fp16 mma, all layers in one grid (8,16,6)
// ======================================================================
#define ASTR 36
#define AQ_OFF 0
#define AK_OFF (128*ASTR)
#define AV_OFF (AK_OFF + 64*ASTR)
#define AP_OFF (AV_OFF + 64*ASTR)
#define ATTN_SMEM ((AP_OFF + 128*ASTR)*4)   // 55296 B

__global__ __launch_bounds__(256) void attn_mma() {
    extern __shared__ uint32_t sm[];
    uint32_t* Qs  = sm + AQ_OFF;
    uint32_t* Ks  = sm + AK_OFF;
    uint32_t* VsT = sm + AV_OFF;
    uint32_t* Ps  = sm + AP_OFF;
    uint32_t sbase = smem_to_u32(sm);
    int tid = threadIdx.x, lane = tid & 31, wid = tid >> 5;
    int qt = blockIdx.x, h = blockIdx.y;
    int z = blockIdx.z;
    int layer = z % NL, b = z / NL;
    int kh = h >> 1;
    int t0 = qt*128, m0 = wid*16;
    int q = lane >> 2, cl = lane & 3;
    const __half* Qsrc = g_Q + (size_t)layer*XN;
    float* Odst = g_O + (size_t)layer*XN;

    // ---- stage Q (pre-scaled at rope) via cp.async ----
    #pragma unroll
    for (int j = 0; j < 4; j++) {
        int f = tid + j*256;            // 0..1023
        int r = f >> 3, seg = f & 7;
        CP16(sbase + (uint32_t)((AQ_OFF + r*ASTR + seg*4)*4),
             Qsrc + ((size_t)(b*TT + t0 + r))*DD + h*HD + seg*8);
    }
    CP_COMMIT(); CP_WAIT(0);

    float occ[8][4];
    #pragma unroll
    for (int nt = 0; nt < 8; nt++)
        #pragma unroll
        for (int e = 0; e < 4; e++) occ[nt][e] = 0.f;
    float m0r = NEGINF, m1r = NEGINF, l0r = 0.f, l1r = 0.f;

    int ntiles = 2*qt + 2 + layer*16;
    int lim0 = t0 + m0 + q + layer*TT;
    int lim1 = lim0 + 8;

    int vl = tid & 31, vw = tid >> 5;       // V staging: lane = kv pair, warp = hd block
    int kv0 = vl*2, vhd0 = vw*8;

    for (int jt = 0; jt < ntiles; jt++) {
        __syncthreads();
        // stage K via cp.async (64 rows x 128 B)
        #pragma unroll
        for (int j = 0; j < 2; j++) {
            int f = tid + j*256;            // 0..511
            int r = f >> 3, seg = f & 7;
            CP16(sbase + (uint32_t)((AK_OFF + r*ASTR + seg*4)*4),
                 g_K + ((size_t)(b*MAXKV + jt*64 + r))*(HKV*HD) + kh*HD + seg*8);
        }
        CP_COMMIT();
        // stage V transposed: VsT[hd][kv] half2-packed along kv
        {
            const __half* vp = g_V + ((size_t)(b*MAXKV + jt*64 + kv0))*(HKV*HD) + kh*HD + vhd0;
            uint4 va = *(const uint4*)vp;
            uint4 vb = *(const uint4*)(vp + HKV*HD);
            const uint32_t* aw = (const uint32_t*)&va;
            const uint32_t* bw = (const uint32_t*)&vb;
            #pragma unroll
            for (int w = 0; w < 4; w++) {
                VsT[(vhd0 + 2*w + 0)*ASTR + vl] = __byte_perm(aw[w], bw[w], 0x5410);
                VsT[(vhd0 + 2*w + 1)*ASTR + vl] = __byte_perm(aw[w], bw[w], 0x7632);
            }
        }
        CP_WAIT(0);
        __syncthreads();

        // ---- S = Q · K^T ----
        float s[8][4];
        #pragma unroll
        for (int nt = 0; nt < 8; nt++) { s[nt][0]=0.f; s[nt][1]=0.f; s[nt][2]=0.f; s[nt][3]=0.f; }
        #pragma unroll
        for (int ks = 0; ks < 4; ks++) {
            uint32_t a[4];
            const uint32_t* ap = Qs + (m0 + q)*ASTR + ks*8 + cl;
            a[0] = ap[0]; a[1] = ap[8*ASTR]; a[2] = ap[4]; a[3] = ap[8*ASTR + 4];
            #pragma unroll
            for (int nt = 0; nt < 8; nt++) {
                const uint32_t* bp = Ks + (nt*8 + q)*ASTR + ks*8 + cl;
                uint32_t bb[2] = { bp[0], bp[4] };
                mma_16n8k16(s[nt], a, bb);
            }
        }

        // ---- mask + online softmax (exp2 domain) ----
        int kbase = jt*64;
        float mx0 = NEGINF, mx1 = NEGINF;
        #pragma unroll
        for (int nt = 0; nt < 8; nt++) {
            int k0 = kbase + nt*8 + 2*cl;
            if (k0     > lim0) s[nt][0] = NEGINF;
            if (k0 + 1 > lim0) s[nt][1] = NEGINF;
            if (k0     > lim1) s[nt][2] = NEGINF;
            if (k0 + 1 > lim1) s[nt][3] = NEGINF;
            mx0 = fmaxf(mx0, fmaxf(s[nt][0], s[nt][1]));
            mx1 = fmaxf(mx1, fmaxf(s[nt][2], s[nt][3]));
        }
        mx0 = fmaxf(mx0, __shfl_xor_sync(0xffffffffu, mx0, 1));
        mx0 = fmaxf(mx0, __shfl_xor_sync(0xffffffffu, mx0, 2));
        mx1 = fmaxf(mx1, __shfl_xor_sync(0xffffffffu, mx1, 1));
        mx1 = fmaxf(mx1, __shfl_xor_sync(0xffffffffu, mx1, 2));
        float mn0 = fmaxf(m0r, mx0), mn1 = fmaxf(m1r, mx1);
        float cor0 = exp2f(m0r - mn0), cor1 = exp2f(m1r - mn1);
        m0r = mn0; m1r = mn1;
        float rs0 = 0.f, rs1 = 0.f;
        #pragma unroll
        for (int nt = 0; nt < 8; nt++) {
            s[nt][0] = exp2f(s[nt][0] - mn0); s[nt][1] = exp2f(s[nt][1] - mn0);
            s[nt][2] = exp2f(s[nt][2] - mn1); s[nt][3] = exp2f(s[nt][3] - mn1);
            rs0 += s[nt][0] + s[nt][1];
            rs1 += s[nt][2] + s[nt][3];
            Ps[(m0 + q)*ASTR + nt*4 + cl]     = packh2(s[nt][0], s[nt][1]);
            Ps[(m0 + q + 8)*ASTR + nt*4 + cl] = packh2(s[nt][2], s[nt][3]);
            occ[nt][0] *= cor0; occ[nt][1] *= cor0;
            occ[nt][2] *= cor1; occ[nt][3] *= cor1;
        }
        rs0 += __shfl_xor_sync(0xffffffffu, rs0, 1);
        rs0 += __shfl_xor_sync(0xffffffffu, rs0, 2);
        rs1 += __shfl_xor_sync(0xffffffffu, rs1, 1);
        rs1 += __shfl_xor_sync(0xffffffffu, rs1, 2);
        l0r = l0r*cor0 + rs0;
        l1r = l1r*cor1 + rs1;

        // ---- O += P · V (warp-private P rows; no extra sync) ----
        #pragma unroll
        for (int ks = 0; ks < 4; ks++) {
            uint32_t a[4];
            const uint32_t* ap = Ps + (m0 + q)*ASTR + ks*8 + cl;
            a[0] = ap[0]; a[1] = ap[8*ASTR]; a[2] = ap[4]; a[3] = ap[8*ASTR + 4];
            #pragma unroll
            for (int nt = 0; nt < 8; nt++) {
                const uint32_t* bp = VsT + (nt*8 + q)*ASTR + ks*8 + cl;
                uint32_t bb[2] = { bp[0], bp[4] };
                mma_16n8k16(occ[nt], a, bb);
            }
        }
    }

    float inv0 = 1.0f / l0r, inv1 = 1.0f / l1r;
    #pragma unroll
    for (int nt = 0; nt < 8; nt++) {
        float* d0 = Odst + ((size_t)(b*TT + t0 + m0 + q))*DD + h*HD + nt*8 + 2*cl;
        *(float2*)d0 = make_float2(occ[nt][0]*inv0, occ[nt][1]*inv0);
        *(float2*)(d0 + 8*DD) = make_float2(occ[nt][2]*inv1, occ[nt][3]*inv1);
    }
}

// ---------------- lambda weights -------------------------------------
__global__ void compute_lw(const float* __restrict__ lam) {
    if (threadIdx.x == 0) {
        float s0 = 1.f/(1.f+expf(-lam[0]));
        float s1 = 1.f/(1.f+expf(-lam[1]));
        float s2 = 1.f/(1.f+expf(-lam[2]));
        float mean = (s0+s1+s2)*(1.f/3.f);
        float d0 = s0-mean, d1 = s1-mean, d2 = s2-mean;
        float var = (d0*d0+d1*d1+d2*d2)*(1.f/3.f);
        float r = rsqrtf(var + EPSI);
        g_lw[0] = d0*r; g_lw[1] = d1*r; g_lw[2] = d2*r;
    }
}

// ---------------- RoPE (all layers), half in/out ----------------------
#define NQROPE (BB*TT*HH*32)
#define NKROPE (BB*TT*HKV*32)
#define QSCALE (0.125f * 1.44269504f)
__global__ void rope_all(const float* __restrict__ cosT, const float* __restrict__ sinT) {
    int idx = blockIdx.x * blockDim.x + threadIdx.x;
    if (idx < NL*NQROPE) {
        int layer = idx >> 20;
        int r = idx & (NQROPE-1);
        int d = r & 31;
        int h = (r >> 5) & 15;
        int t = (r >> 9) & 1023;
        int b = r >> 19;
        size_t base = (size_t)layer*XN + ((size_t)(b*TT + t))*DD + h*HD + d;
        float x1 = __half2float(g_Q[base]), x2 = __half2float(g_Q[base + 32]);
        float c = cosT[t*32 + d], s = sinT[t*32 + d];
        g_Q[base]      = __float2half_rn((x1*c - x2*s)*QSCALE);
        g_Q[base + 32] = __float2half_rn((x2*c + x1*s)*QSCALE);
    } else {
        int j = idx - NL*NQROPE;
        int layer = j >> 19;
        int k = j & (NKROPE-1);
        int d  = k & 31;
        int kh = (k >> 5) & 7;
        int t  = (k >> 8) & 1023;
        int b  = k >> 18;
        int p  = layer*TT + t;
        size_t base = ((size_t)(b*MAXKV + p))*(HKV*HD) + kh*HD + d;
        float x1 = __half2float(g_K[base]), x2 = __half2float(g_K[base + 32]);
        float c = cosT[p*32 + d], s = sinT[p*32 + d];
        g_K[base]      = __float2half_rn(x1*c - x2*s);
        g_K[base + 32] = __float2half_rn(x2*c + x1*s);
    }
}
#define ROPE_THREADS (NL*(NQROPE + NKROPE))

// ---------------- fused 3x rmsnorm + residual + final norm ------------
__device__ __forceinline__ float block_reduce_sum(float v, float* red, int tid) {
    v += __shfl_xor_sync(0xffffffffu, v, 16);
    v += __shfl_xor_sync(0xffffffffu, v, 8);
    v += __shfl_xor_sync(0xffffffffu, v, 4);
    v += __shfl_xor_sync(0xffffffffu, v, 2);
    v += __shfl_xor_sync(0xffffffffu, v, 1);
    if ((tid & 31) == 0) red[tid >> 5] = v;
    __syncthreads();
    if (tid < 32) {
        float w = (tid < 8) ? red[tid] : 0.f;
        w += __shfl_xor_sync(0xffffffffu, w, 4);
        w += __shfl_xor_sync(0xffffffffu, w, 2);
        w += __shfl_xor_sync(0xffffffffu, w, 1);
        if (tid == 0) red[0] = w;
    }
    __syncthreads();
    return red[0];
}

__global__ __launch_bounds__(256) void acc_final(const float* __restrict__ x,
                                                 const float* __restrict__ lnw,
                                                 const float* __restrict__ flnw,
                                                 const float* __restrict__ alpha) {
    __shared__ float red[4][8];
    int row = blockIdx.x, tid = threadIdx.x;
    float4 o0 = *(const float4*)(g_O + 0*(size_t)XN + (size_t)row*DD + tid*4);
    float4 o1 = *(const float4*)(g_O + 1*(size_t)XN + (size_t)row*DD + tid*4);
    float4 o2 = *(const float4*)(g_O + 2*(size_t)XN + (size_t)row*DD + tid*4);
    float ss0 = o0.x*o0.x + o0.y*o0.y + o0.z*o0.z + o0.w*o0.w;
    float ss1 = o1.x*o1.x + o1.y*o1.y + o1.z*o1.z + o1.w*o1.w;
    float ss2 = o2.x*o2.x + o2.y*o2.y + o2.z*o2.z + o2.w*o2.w;
    float r0 = rsqrtf(block_reduce_sum(ss0, red[0], tid) * (1.0f/DD) + EPSI) * g_lw[0];
    float r1 = rsqrtf(block_reduce_sum(ss1, red[1], tid) * (1.0f/DD) + EPSI) * g_lw[1];
    float r2 = rsqrtf(block_reduce_sum(ss2, red[2], tid) * (1.0f/DD) + EPSI) * g_lw[2];
    float4 w0 = *(const float4*)(lnw + 0*DD + tid*4);
    float4 w1 = *(const float4*)(lnw + 1*DD + tid*4);
    float4 w2 = *(const float4*)(lnw + 2*DD + tid*4);
    float al = alpha[0];
    float4 xv = *(const float4*)(x + (size_t)row*DD + tid*4);
    float4 v;
    v.x = o0.x*r0*w0.x + o1.x*r1*w1.x + o2.x*r2*w2.x + al*xv.x;
    v.y = o0.y*r0*w0.y + o1.y*r1*w1.y + o2.y*r2*w2.y + al*xv.y;
    v.z = o0.z*r0*w0.z + o1.z*r1*w1.z + o2.z*r2*w2.z + al*xv.z;
    v.w = o0.w*r0*w0.w + o1.w*r1*w1.w + o2.w*r2*w2.w + al*xv.w;
    float ss = v.x*v.x + v.y*v.y + v.z*v.z + v.w*v.w;
    float r = rsqrtf(block_reduce_sum(ss, red[3], tid) * (1.0f/DD) + EPSI);
    float4 fw = *(const float4*)(flnw + tid*4);
    uint2 res;
    res.x = packh2(v.x*r*fw.x, v.y*r*fw.y);
    res.y = packh2(v.z*r*fw.z, v.w*r*fw.w);
    *(uint2*)(g_y + (size_t)row*DD + tid*4) = res;
}

// ---------------- launch ---------------------------------------------
extern "C" void kernel_launch(void* const* d_in, const int* in_sizes, int n_in,
                              void* d_out, int out_size) {
    const float* x    = (const float*)d_in[0];
    const float* cosT = (const float*)d_in[1];
    const float* sinT = (const float*)d_in[2];
    const float* lnw  = (const float*)d_in[6];
    const float* lam  = (const float*)d_in[7];
    const float* flnw = (const float*)d_in[9];
    const float* alpha= (const float*)d_in[10];
    float* out = (float*)d_out;

    cudaFuncSetAttribute(qkv_gemm_tc, cudaFuncAttributeMaxDynamicSharedMemorySize, GEMM_SMEM);
    cudaFuncSetAttribute(out_gemm_tc, cudaFuncAttributeMaxDynamicSharedMemorySize, GEMM_SMEM);
    cudaFuncSetAttribute(attn_mma,    cudaFuncAttributeMaxDynamicSharedMemorySize, ATTN_SMEM);

    compute_lw<<<1, 32>>>(lam);
    convert_inputs<<<CONV_BLOCKS, 256>>>(x, (const float*)d_in[3], (const float*)d_in[4],
                                         (const float*)d_in[5], (const float*)d_in[8]);

    qkv_gemm_tc<<<dim3(16, 16, NL), 256, GEMM_SMEM>>>();
    rope_all<<<ROPE_THREADS/256, 256>>>(cosT, sinT);
    attn_mma<<<dim3(8, HH, BB*NL), 256, ATTN_SMEM>>>();
    acc_final<<<BB*TT, 256>>>(x, lnw, flnw, alpha);
    out_gemm_tc<<<dim3(16, 8), 256, GEMM_SMEM>>>(out);
}

// round 17
// speedup vs baseline: 4.4743x; 1.0331x over previous
#include <cuda_runtime.h>
#include <cuda_fp16.h>
#include <math.h>
#include <cstdint>

#define BB 2
#define TT 1024
#define DD 1024
#define HH 16
#define HKV 8
#define HD 64
#define NL 3
#define MAXKV 3072
#define EPSI 1e-5f
#define NEGINF (-1e30f)

#define XN  (BB*TT*DD)
#define QWN (NL*DD*DD)
#define KWN (NL*(DD/2)*DD)
#define OWN (DD*DD)

// ---------------- device scratch (static; no allocation) ----------------
__device__ __half g_Q[NL*XN];                // roped Q (half), all layers
__device__ __half g_K[BB*MAXKV*HKV*HD];      // roped K cache (half)
__device__ __half g_V[BB*MAXKV*HKV*HD];      // V cache (half)
__device__ float  g_O[NL*XN];                // attention out (fp32)
__device__ __half g_y[XN];                   // pre-outproj (half)
__device__ float  g_lw[NL];

// half copies of GEMM inputs (cp.async stages raw bits)
__device__ __half g_xh[XN];
__device__ __half g_qwh[QWN];
__device__ __half g_kwh[KWN];
__device__ __half g_vwh[KWN];
__device__ __half g_owh[OWN];

// ================= helpers ============================================
__device__ __forceinline__ uint32_t smem_to_u32(const void* p) {
    uint32_t a;
    asm("{ .reg .u64 t; cvta.to.shared.u64 t, %1; cvt.u32.u64 %0, t; }" : "=r"(a) : "l"(p));
    return a;
}
#define CP16(dst, src) \
    asm volatile("cp.async.cg.shared.global [%0], [%1], 16;" :: "r"(dst), "l"(src))
#define CP_COMMIT() asm volatile("cp.async.commit_group;" ::: "memory")
#define CP_WAIT(n)  asm volatile("cp.async.wait_group %0;" :: "n"(n) : "memory")

__device__ __forceinline__ void mma_16n8k16(float c[4], const uint32_t a[4], const uint32_t b[2]) {
    asm volatile("mma.sync.aligned.m16n8k16.row.col.f32.f16.f16.f32 "
        "{%0,%1,%2,%3}, {%4,%5,%6,%7}, {%8,%9}, {%0,%1,%2,%3};"
        : "+f"(c[0]), "+f"(c[1]), "+f"(c[2]), "+f"(c[3])
        : "r"(a[0]), "r"(a[1]), "r"(a[2]), "r"(a[3]), "r"(b[0]), "r"(b[1]));
}
__device__ __forceinline__ uint32_t packh2(float lo, float hi) {
    __half2 h = __floats2half2_rn(lo, hi);
    return *(uint32_t*)&h;
}

// ---------------- input conversion (once per launch) ------------------
__global__ void convert_inputs(const float* __restrict__ x,  const float* __restrict__ qw,
                               const float* __restrict__ kw, const float* __restrict__ vw,
                               const float* __restrict__ ow) {
    int n = (blockIdx.x*blockDim.x + threadIdx.x)*8;
    const float* src; __half* dst; int off;
    if      (n < XN)                  { src = x;  dst = g_xh;  off = n; }
    else if (n < XN+QWN)              { src = qw; dst = g_qwh; off = n-XN; }
    else if (n < XN+QWN+KWN)          { src = kw; dst = g_kwh; off = n-XN-QWN; }
    else if (n < XN+QWN+2*KWN)        { src = vw; dst = g_vwh; off = n-XN-QWN-KWN; }
    else                              { src = ow; dst = g_owh; off = n-XN-QWN-2*KWN; }
    float4 v0 = *(const float4*)(src + off);
    float4 v1 = *(const float4*)(src + off + 4);
    uint4 u;
    u.x = packh2(v0.x, v0.y); u.y = packh2(v0.z, v0.w);
    u.z = packh2(v1.x, v1.y); u.w = packh2(v1.z, v1.w);
    *(uint4*)(dst + off) = u;
}
#define CONV_BLOCKS ((XN+QWN+2*KWN+OWN)/8/256)

// ======================================================================
//      GEMM: fp16 m16n8k16, cp.async double-buffered, K-chunk 64
// ======================================================================
#define SSTRIDE 36
#define GWORDS (128*SSTRIDE)
#define GEMM_SMEM (2*2*GWORDS*4)

__device__ __forceinline__ void stage_ca(const __half* __restrict__ A,
                                         const __half* __restrict__ W,
                                         uint32_t sbase, int buf, int kt, int tid) {
    #pragma unroll
    for (int j = 0; j < 4; j++) {
        int f = tid + j*256;
        int r = f >> 3, seg = f & 7;
        uint32_t d = sbase + (uint32_t)((buf*2*GWORDS + r*SSTRIDE + seg*4)*4);
        CP16(d,             A + (size_t)r*DD + kt*64 + seg*8);
        CP16(d + GWORDS*4,  W + (size_t)r*DD + kt*64 + seg*8);
    }
}

__device__ __forceinline__ void compute_chunk(const uint32_t* __restrict__ As,
                                              const uint32_t* __restrict__ Ws,
                                              float c[4][4][4], int lane, int wm0, int wn0) {
    int q = lane >> 2, cl = lane & 3;
    #pragma unroll
    for (int ks = 0; ks < 4; ks++) {
        int k0 = ks*8;
        uint32_t a[4][4], b[4][2];
        #pragma unroll
        for (int mi = 0; mi < 4; mi++) {
            int row = wm0 + mi*16 + q;
            const uint32_t* p = As + row*SSTRIDE + k0 + cl;
            a[mi][0] = p[0];
            a[mi][1] = p[8*SSTRIDE];
            a[mi][2] = p[4];
            a[mi][3] = p[8*SSTRIDE + 4];
        }
        #pragma unroll
        for (int ni = 0; ni < 4; ni++) {
            int coln = wn0 + ni*8 + q;
            const uint32_t* p = Ws + coln*SSTRIDE + k0 + cl;
            b[ni][0] = p[0];
            b[ni][1] = p[4];
        }
        #pragma unroll
        for (int mi = 0; mi < 4; mi++)
            #pragma unroll
            for (int ni = 0; ni < 4; ni++)
                mma_16n8k16(c[mi][ni], a[mi], b[ni]);
    }
}

__device__ __forceinline__ void h16_mainloop(const __half* __restrict__ A,
                                             const __half* __restrict__ W,
                                             uint32_t* sh, float c[4][4][4],
                                             int tid, int lane, int wm0, int wn0) {
    uint32_t sbase = smem_to_u32(sh);
    stage_ca(A, W, sbase, 0, 0, tid); CP_COMMIT();
    for (int kt = 0; kt < 16; kt++) {
        int buf = kt & 1;
        if (kt < 15) { stage_ca(A, W, sbase, buf^1, kt+1, tid); CP_COMMIT(); CP_WAIT(1); }
        else         { CP_WAIT(0); }
        __syncthreads();
        compute_chunk(sh + buf*2*GWORDS, sh + buf*2*GWORDS + GWORDS, c, lane, wm0, wn0);
        __syncthreads();
    }
}

// grid (16, 16, NL)
__global__ __launch_bounds__(256) void qkv_gemm_tc() {
    extern __shared__ uint32_t sh[];
    int tid = threadIdx.x, lane = tid & 31, wid = tid >> 5;
    int wm0 = (wid >> 2)*64, wn0 = (wid & 3)*32;
    int bm = blockIdx.x, bn = blockIdx.y, layer = blockIdx.z;
    const __half* A = g_xh + (size_t)bm*128*DD;
    const __half* W;
    int mode, lc0;
    if (bn < 8)       { W = g_qwh + (size_t)layer*DD*DD     + (size_t)bn*128*DD;      mode = 0; lc0 = bn*128; }
    else if (bn < 12) { W = g_kwh + (size_t)layer*(DD/2)*DD + (size_t)(bn-8)*128*DD;  mode = 1; lc0 = (bn-8)*128; }
    else              { W = g_vwh + (size_t)layer*(DD/2)*DD + (size_t)(bn-12)*128*DD; mode = 2; lc0 = (bn-12)*128; }

    float c[4][4][4];
    #pragma unroll
    for (int mi = 0; mi < 4; mi++)
        #pragma unroll
        for (int ni = 0; ni < 4; ni++)
            #pragma unroll
            for (int q = 0; q < 4; q++) c[mi][ni][q] = 0.f;

    h16_mainloop(A, W, sh, c, tid, lane, wm0, wn0);

    __half* kvbase = (mode == 1) ? g_K : g_V;
    #pragma unroll
    for (int mi = 0; mi < 4; mi++) {
        #pragma unroll
        for (int half = 0; half < 2; half++) {
            int mrow = bm*128 + wm0 + mi*16 + half*8 + (lane >> 2);
            __half* dst;
            if (mode == 0) {
                dst = g_Q + (size_t)layer*XN + (size_t)mrow*DD + lc0;
            } else {
                int b = mrow >> 10, t = mrow & 1023;
                dst = kvbase + ((size_t)(b*MAXKV + layer*TT + t))*(HKV*HD) + lc0;
            }
            #pragma unroll
            for (int ni = 0; ni < 4; ni++) {
                int col = wn0 + ni*8 + (lane & 3)*2;
                uint32_t v = half ? packh2(c[mi][ni][2], c[mi][ni][3])
                                  : packh2(c[mi][ni][0], c[mi][ni][1]);
                *(uint32_t*)(dst + col) = v;
            }
        }
    }
}

__global__ __launch_bounds__(256) void out_gemm_tc(float* __restrict__ out) {
    extern __shared__ uint32_t sh[];
    int tid = threadIdx.x, lane = tid & 31, wid = tid >> 5;
    int wm0 = (wid >> 2)*64, wn0 = (wid & 3)*32;
    int bm = blockIdx.x, bn = blockIdx.y;
    const __half* A = g_y + (size_t)bm*128*DD;
    const __half* W = g_owh + (size_t)bn*128*DD;

    float c[4][4][4];
    #pragma unroll
    for (int mi = 0; mi < 4; mi++)
        #pragma unroll
        for (int ni = 0; ni < 4; ni++)
            #pragma unroll
            for (int q = 0; q < 4; q++) c[mi][ni][q] = 0.f;

    h16_mainloop(A, W, sh, c, tid, lane, wm0, wn0);

    #pragma unroll
    for (int mi = 0; mi < 4; mi++) {
        #pragma unroll
        for (int half = 0; half < 2; half++) {
            int mrow = bm*128 + wm0 + mi*16 + half*8 + (lane >> 2);
            float* dst = out + (size_t)mrow*DD + bn*128;
            #pragma unroll
            for (int ni = 0; ni < 4; ni++) {
                int col = wn0 + ni*8 + (lane & 3)*2;
                float2 v = half ? make_float2(c[mi][ni][2], c[mi][ni][3])
                                : make_float2(c[mi][ni][0], c[mi][ni][1]);
                *(float2*)(dst + col) = v;
            }
        }
    }
}

// ======================================================================
//   Flash attention fp16 mma, double-buffered KV, grid (8,16,6)
// ======================================================================
#define ASTR 36
#define AQ_OFF 0
#define AKV0_OFF (128*ASTR)                 // buffer0: K[64*ASTR] then VsT[64*ASTR]
#define AKV1_OFF (AKV0_OFF + 2*64*ASTR)     // buffer1
#define AP_OFF   (AKV1_OFF + 2*64*ASTR)
#define ATTN_SMEM ((AP_OFF + 128*ASTR)*4)   // 73728 B

__global__ __launch_bounds__(256) void attn_mma() {
    extern __shared__ uint32_t sm[];
    uint32_t* Qs = sm + AQ_OFF;
    uint32_t* Ps = sm + AP_OFF;
    uint32_t sbase = smem_to_u32(sm);
    int tid = threadIdx.x, lane = tid & 31, wid = tid >> 5;
    int qt = blockIdx.x, h = blockIdx.y;
    int z = blockIdx.z;
    int layer = z % NL, b = z / NL;
    int kh = h >> 1;
    int t0 = qt*128, m0 = wid*16;
    int q = lane >> 2, cl = lane & 3;
    const __half* Qsrc = g_Q + (size_t)layer*XN;
    float* Odst = g_O + (size_t)layer*XN;

    int vl = tid & 31, vw = tid >> 5;       // V staging: lane -> kv pair, warp -> hd block
    int kv0 = vl*2, vhd0 = vw*8;

    // ---- prologue: Q + K(0) in one cp.async group; V(0) direct ----
    #pragma unroll
    for (int j = 0; j < 4; j++) {
        int f = tid + j*256;
        int r = f >> 3, seg = f & 7;
        CP16(sbase + (uint32_t)((AQ_OFF + r*ASTR + seg*4)*4),
             Qsrc + ((size_t)(b*TT + t0 + r))*DD + h*HD + seg*8);
    }
    #pragma unroll
    for (int j = 0; j < 2; j++) {
        int f = tid + j*256;
        int r = f >> 3, seg = f & 7;
        CP16(sbase + (uint32_t)((AKV0_OFF + r*ASTR + seg*4)*4),
             g_K + ((size_t)(b*MAXKV + r))*(HKV*HD) + kh*HD + seg*8);
    }
    CP_COMMIT();
    {   // V(0) -> buf0 (no reader yet)
        const __half* vp = g_V + ((size_t)(b*MAXKV + kv0))*(HKV*HD) + kh*HD + vhd0;
        uint4 va = *(const uint4*)vp;
        uint4 vb = *(const uint4*)(vp + HKV*HD);
        const uint32_t* aw = (const uint32_t*)&va;
        const uint32_t* bw = (const uint32_t*)&vb;
        uint32_t* VsT = sm + AKV0_OFF + 64*ASTR;
        #pragma unroll
        for (int w = 0; w < 4; w++) {
            VsT[(vhd0 + 2*w + 0)*ASTR + vl] = __byte_perm(aw[w], bw[w], 0x5410);
            VsT[(vhd0 + 2*w + 1)*ASTR + vl] = __byte_perm(aw[w], bw[w], 0x7632);
        }
    }

    float occ[8][4];
    #pragma unroll
    for (int nt = 0; nt < 8; nt++)
        #pragma unroll
        for (int e = 0; e < 4; e++) occ[nt][e] = 0.f;
    float m0r = NEGINF, m1r = NEGINF, l0r = 0.f, l1r = 0.f;

    int ntiles = 2*qt + 2 + layer*16;
    int lim0 = t0 + m0 + q + layer*TT;
    int lim1 = lim0 + 8;

    for (int jt = 0; jt < ntiles; jt++) {
        int buf = jt & 1;
        uint32_t* Ks  = sm + (buf ? AKV1_OFF : AKV0_OFF);
        uint32_t* VsT = Ks + 64*ASTR;
        uint32_t* KsN = sm + (buf ? AKV0_OFF : AKV1_OFF);
        uint32_t* VsN = KsN + 64*ASTR;

        // prefetch next tile: K via cp.async, V into registers (STS after compute)
        uint4 va, vb;
        bool have_next = (jt + 1 < ntiles);
        if (have_next) {
            uint32_t koff = (uint32_t)((KsN - sm) * 4);
            #pragma unroll
            for (int j = 0; j < 2; j++) {
                int f = tid + j*256;
                int r = f >> 3, seg = f & 7;
                CP16(sbase + koff + (uint32_t)((r*ASTR + seg*4)*4),
                     g_K + ((size_t)(b*MAXKV + (jt+1)*64 + r))*(HKV*HD) + kh*HD + seg*8);
            }
            CP_COMMIT();
            const __half* vp = g_V + ((size_t)(b*MAXKV + (jt+1)*64 + kv0))*(HKV*HD) + kh*HD + vhd0;
            va = *(const uint4*)vp;
            vb = *(const uint4*)(vp + HKV*HD);
            CP_WAIT(1);
        } else {
            CP_WAIT(0);
        }
        __syncthreads();

        // ---- S = Q · K^T ----
        float s[8][4];
        #pragma unroll
        for (int nt = 0; nt < 8; nt++) { s[nt][0]=0.f; s[nt][1]=0.f; s[nt][2]=0.f; s[nt][3]=0.f; }
        #pragma unroll
        for (int ks = 0; ks < 4; ks++) {
            uint32_t a[4];
            const uint32_t* ap = Qs + (m0 + q)*ASTR + ks*8 + cl;
            a[0] = ap[0]; a[1] = ap[8*ASTR]; a[2] = ap[4]; a[3] = ap[8*ASTR + 4];
            #pragma unroll
            for (int nt = 0; nt < 8; nt++) {
                const uint32_t* bp = Ks + (nt*8 + q)*ASTR + ks*8 + cl;
                uint32_t bb[2] = { bp[0], bp[4] };
                mma_16n8k16(s[nt], a, bb);
            }
        }

        // ---- mask + online softmax (exp2 domain) ----
        int kbase = jt*64;
        float mx0 = NEGINF, mx1 = NEGINF;
        #pragma unroll
        for (int nt = 0; nt < 8; nt++) {
            int k0 = kbase + nt*8 + 2*cl;
            if (k0     > lim0) s[nt][0] = NEGINF;
            if (k0 + 1 > lim0) s[nt][1] = NEGINF;
            if (k0     > lim1) s[nt][2] = NEGINF;
            if (k0 + 1 > lim1) s[nt][3] = NEGINF;
            mx0 = fmaxf(mx0, fmaxf(s[nt][0], s[nt][1]));
            mx1 = fmaxf(mx1, fmaxf(s[nt][2], s[nt][3]));
        }
        mx0 = fmaxf(mx0, __shfl_xor_sync(0xffffffffu, mx0, 1));
        mx0 = fmaxf(mx0, __shfl_xor_sync(0xffffffffu, mx0, 2));
        mx1 = fmaxf(mx1, __shfl_xor_sync(0xffffffffu, mx1, 1));
        mx1 = fmaxf(mx1, __shfl_xor_sync(0xffffffffu, mx1, 2));
        float mn0 = fmaxf(m0r, mx0), mn1 = fmaxf(m1r, mx1);
        float cor0 = exp2f(m0r - mn0), cor1 = exp2f(m1r - mn1);
        m0r = mn0; m1r = mn1;
        float rs0 = 0.f, rs1 = 0.f;
        #pragma unroll
        for (int nt = 0; nt < 8; nt++) {
            s[nt][0] = exp2f(s[nt][0] - mn0); s[nt][1] = exp2f(s[nt][1] - mn0);
            s[nt][2] = exp2f(s[nt][2] - mn1); s[nt][3] = exp2f(s[nt][3] - mn1);
            rs0 += s[nt][0] + s[nt][1];
            rs1 += s[nt][2] + s[nt][3];
            Ps[(m0 + q)*ASTR + nt*4 + cl]     = packh2(s[nt][0], s[nt][1]);
            Ps[(m0 + q + 8)*ASTR + nt*4 + cl] = packh2(s[nt][2], s[nt][3]);
            occ[nt][0] *= cor0; occ[nt][1] *= cor0;
            occ[nt][2] *= cor1; occ[nt][3] *= cor1;
        }
        rs0 += __shfl_xor_sync(0xffffffffu, rs0, 1);
        rs0 += __shfl_xor_sync(0xffffffffu, rs0, 2);
        rs1 += __shfl_xor_sync(0xffffffffu, rs1, 1);
        rs1 += __shfl_xor_sync(0xffffffffu, rs1, 2);
        l0r = l0r*cor0 + rs0;
        l1r = l1r*cor1 + rs1;

        // ---- O += P · V ----
        #pragma unroll
        for (int ks = 0; ks < 4; ks++) {
            uint32_t a[4];
            const uint32_t* ap = Ps + (m0 + q)*ASTR + ks*8 + cl;
            a[0] = ap[0]; a[1] = ap[8*ASTR]; a[2] = ap[4]; a[3] = ap[8*ASTR + 4];
            #pragma unroll
            for (int nt = 0; nt < 8; nt++) {
                const uint32_t* bp = VsT + (nt*8 + q)*ASTR + ks*8 + cl;
                uint32_t bb[2] = { bp[0], bp[4] };
                mma_16n8k16(occ[nt], a, bb);
            }
        }
        __syncthreads();

        // ---- deferred V store for next tile ----
        if (have_next) {
            const uint32_t* aw = (const uint32_t*)&va;
            const uint32_t* bw = (const uint32_t*)&vb;
            #pragma unroll
            for (int w = 0; w < 4; w++) {
                VsN[(vhd0 + 2*w + 0)*ASTR + vl] = __byte_perm(aw[w], bw[w], 0x5410);
                VsN[(vhd0 + 2*w + 1)*ASTR + vl] = __byte_perm(aw[w], bw[w], 0x7632);
            }
        }
    }

    float inv0 = 1.0f / l0r, inv1 = 1.0f / l1r;
    #pragma unroll
    for (int nt = 0; nt < 8; nt++) {
        float* d0 = Odst + ((size_t)(b*TT + t0 + m0 + q))*DD + h*HD + nt*8 + 2*cl;
        *(float2*)d0 = make_float2(occ[nt][0]*inv0, occ[nt][1]*inv0);
        *(float2*)(d0 + 8*DD) = make_float2(occ[nt][2]*inv1, occ[nt][3]*inv1);
    }
}

// ---------------- lambda weights -------------------------------------
__global__ void compute_lw(const float* __restrict__ lam) {
    if (threadIdx.x == 0) {
        float s0 = 1.f/(1.f+expf(-lam[0]));
        float s1 = 1.f/(1.f+expf(-lam[1]));
        float s2 = 1.f/(1.f+expf(-lam[2]));
        float mean = (s0+s1+s2)*(1.f/3.f);
        float d0 = s0-mean, d1 = s1-mean, d2 = s2-mean;
        float var = (d0*d0+d1*d1+d2*d2)*(1.f/3.f);
        float r = rsqrtf(var + EPSI);
        g_lw[0] = d0*r; g_lw[1] = d1*r; g_lw[2] = d2*r;
    }
}

// ---------------- RoPE (all layers), half in/out ----------------------
#define NQROPE (BB*TT*HH*32)
#define NKROPE (BB*TT*HKV*32)
#define QSCALE (0.125f * 1.44269504f)
__global__ void rope_all(const float* __restrict__ cosT, const float* __restrict__ sinT) {
    int idx = blockIdx.x * blockDim.x + threadIdx.x;
    if (idx < NL*NQROPE) {
        int layer = idx >> 20;
        int r = idx & (NQROPE-1);
        int d = r & 31;
        int h = (r >> 5) & 15;
        int t = (r >> 9) & 1023;
        int b = r >> 19;
        size_t base = (size_t)layer*XN + ((size_t)(b*TT + t))*DD + h*HD + d;
        float x1 = __half2float(g_Q[base]), x2 = __half2float(g_Q[base + 32]);
        float c = cosT[t*32 + d], s = sinT[t*32 + d];
        g_Q[base]      = __float2half_rn((x1*c - x2*s)*QSCALE);
        g_Q[base + 32] = __float2half_rn((x2*c + x1*s)*QSCALE);
    } else {
        int j = idx - NL*NQROPE;
        int layer = j >> 19;
        int k = j & (NKROPE-1);
        int d  = k & 31;
        int kh = (k >> 5) & 7;
        int t  = (k >> 8) & 1023;
        int b  = k >> 18;
        int p  = layer*TT + t;
        size_t base = ((size_t)(b*MAXKV + p))*(HKV*HD) + kh*HD + d;
        float x1 = __half2float(g_K[base]), x2 = __half2float(g_K[base + 32]);
        float c = cosT[p*32 + d], s = sinT[p*32 + d];
        g_K[base]      = __float2half_rn(x1*c - x2*s);
        g_K[base + 32] = __float2half_rn(x2*c + x1*s);
    }
}
#define ROPE_THREADS (NL*(NQROPE + NKROPE))

// ---------------- fused 3x rmsnorm + residual + final norm ------------
__device__ __forceinline__ float block_reduce_sum(float v, float* red, int tid) {
    v += __shfl_xor_sync(0xffffffffu, v, 16);
    v += __shfl_xor_sync(0xffffffffu, v, 8);
    v += __shfl_xor_sync(0xffffffffu, v, 4);
    v += __shfl_xor_sync(0xffffffffu, v, 2);
    v += __shfl_xor_sync(0xffffffffu, v, 1);
    if ((tid & 31) == 0) red[tid >> 5] = v;
    __syncthreads();
    if (tid < 32) {
        float w = (tid < 8) ? red[tid] : 0.f;
        w += __shfl_xor_sync(0xffffffffu, w, 4);
        w += __shfl_xor_sync(0xffffffffu, w, 2);
        w += __shfl_xor_sync(0xffffffffu, w, 1);
        if (tid == 0) red[0] = w;
    }
    __syncthreads();
    return red[0];
}

__global__ __launch_bounds__(256) void acc_final(const float* __restrict__ x,
                                                 const float* __restrict__ lnw,
                                                 const float* __restrict__ flnw,
                                                 const float* __restrict__ alpha) {
    __shared__ float red[4][8];
    int row = blockIdx.x, tid = threadIdx.x;
    float4 o0 = *(const float4*)(g_O + 0*(size_t)XN + (size_t)row*DD + tid*4);
    float4 o1 = *(const float4*)(g_O + 1*(size_t)XN + (size_t)row*DD + tid*4);
    float4 o2 = *(const float4*)(g_O + 2*(size_t)XN + (size_t)row*DD + tid*4);
    float ss0 = o0.x*o0.x + o0.y*o0.y + o0.z*o0.z + o0.w*o0.w;
    float ss1 = o1.x*o1.x + o1.y*o1.y + o1.z*o1.z + o1.w*o1.w;
    float ss2 = o2.x*o2.x + o2.y*o2.y + o2.z*o2.z + o2.w*o2.w;
    float r0 = rsqrtf(block_reduce_sum(ss0, red[0], tid) * (1.0f/DD) + EPSI) * g_lw[0];
    float r1 = rsqrtf(block_reduce_sum(ss1, red[1], tid) * (1.0f/DD) + EPSI) * g_lw[1];
    float r2 = rsqrtf(block_reduce_sum(ss2, red[2], tid) * (1.0f/DD) + EPSI) * g_lw[2];
    float4 w0 = *(const float4*)(lnw + 0*DD + tid*4);
    float4 w1 = *(const float4*)(lnw + 1*DD + tid*4);
    float4 w2 = *(const float4*)(lnw + 2*DD + tid*4);
    float al = alpha[0];
    float4 xv = *(const float4*)(x + (size_t)row*DD + tid*4);
    float4 v;
    v.x = o0.x*r0*w0.x + o1.x*r1*w1.x + o2.x*r2*w2.x + al*xv.x;
    v.y = o0.y*r0*w0.y + o1.y*r1*w1.y + o2.y*r2*w2.y + al*xv.y;
    v.z = o0.z*r0*w0.z + o1.z*r1*w1.z + o2.z*r2*w2.z + al*xv.z;
    v.w = o0.w*r0*w0.w + o1.w*r1*w1.w + o2.w*r2*w2.w + al*xv.w;
    float ss = v.x*v.x + v.y*v.y + v.z*v.z + v.w*v.w;
    float r = rsqrtf(block_reduce_sum(ss, red[3], tid) * (1.0f/DD) + EPSI);
    float4 fw = *(const float4*)(flnw + tid*4);
    uint2 res;
    res.x = packh2(v.x*r*fw.x, v.y*r*fw.y);
    res.y = packh2(v.z*r*fw.z, v.w*r*fw.w);
    *(uint2*)(g_y + (size_t)row*DD + tid*4) = res;
}

// ---------------- launch ---------------------------------------------
extern "C" void kernel_launch(void* const* d_in, const int* in_sizes, int n_in,
                              void* d_out, int out_size) {
    const float* x    = (const float*)d_in[0];
    const float* cosT = (const float*)d_in[1];
    const float* sinT = (const float*)d_in[2];
    const float* lnw  = (const float*)d_in[6];
    const float* lam  = (const float*)d_in[7];
    const float* flnw = (const float*)d_in[9];
    const float* alpha= (const float*)d_in[10];
    float* out = (float*)d_out;

    cudaFuncSetAttribute(qkv_gemm_tc, cudaFuncAttributeMaxDynamicSharedMemorySize, GEMM_SMEM);
    cudaFuncSetAttribute(out_gemm_tc, cudaFuncAttributeMaxDynamicSharedMemorySize, GEMM_SMEM);
    cudaFuncSetAttribute(attn_mma,    cudaFuncAttributeMaxDynamicSharedMemorySize, ATTN_SMEM);

    compute_lw<<<1, 32>>>(lam);
    convert_inputs<<<CONV_BLOCKS, 256>>>(x, (const float*)d_in[3], (const float*)d_in[4],
                                         (const float*)d_in[5], (const float*)d_in[8]);

    qkv_gemm_tc<<<dim3(16, 16, NL), 256, GEMM_SMEM>>>();
    rope_all<<<ROPE_THREADS/256, 256>>>(cosT, sinT);
    attn_mma<<<dim3(8, HH, BB*NL), 256, ATTN_SMEM>>>();
    acc_final<<<BB*TT, 256>>>(x, lnw, flnw, alpha);
    out_gemm_tc<<<dim3(16, 8), 256, GEMM_SMEM>>>(out);
}